// round 7
// baseline (speedup 1.0000x reference)
#include <cuda_runtime.h>
#include <cuda_bf16.h>
#include <cstdint>
#include <cstddef>

// Problem constants
#define BB   2
#define SS   2048
#define DD   1024
#define HH   16
#define DK   64
#define MROWS (BB*SS)          // 4096
#define ASLOT (MROWS*DD)       // 4M elements
#define WSLOT (DD*DD)          // 1M elements

// ---------------------------------------------------------------------------
// Scratch (__device__ globals; allocation-free rule)
// ---------------------------------------------------------------------------
__device__ __nv_bfloat16 g_xh[3*ASLOT];    // activation hi (Q,K,V inputs)
__device__ __nv_bfloat16 g_xl[3*ASLOT];
__device__ __nv_bfloat16 g_ph[3*ASLOT];    // projected q,k,v hi
__device__ __nv_bfloat16 g_pl[3*ASLOT];
__device__ __nv_bfloat16 g_oh[ASLOT];      // attention out hi
__device__ __nv_bfloat16 g_ol[ASLOT];
__device__ __nv_bfloat16 g_bh[4*WSLOT];    // W^T hi [n][k], 4 weights
__device__ __nv_bfloat16 g_bl[4*WSLOT];

// ---------------------------------------------------------------------------
// PTX helpers (base sm_103-safe: cp.async, ldmatrix, mma.sync only)
// ---------------------------------------------------------------------------
__device__ __forceinline__ uint32_t smem_u32(const void* p) {
    return (uint32_t)__cvta_generic_to_shared(p);
}

__device__ __forceinline__ void cpa16(uint32_t dst, const void* src) {
    asm volatile("cp.async.cg.shared.global [%0], [%1], 16;" :: "r"(dst), "l"(src) : "memory");
}
#define CP_COMMIT() asm volatile("cp.async.commit_group;" ::: "memory")
#define CP_WAIT0()  asm volatile("cp.async.wait_group 0;" ::: "memory")
#define CP_WAIT1()  asm volatile("cp.async.wait_group 1;" ::: "memory")

__device__ __forceinline__ void ldsm_x4(uint32_t& r0, uint32_t& r1, uint32_t& r2, uint32_t& r3,
                                        uint32_t addr) {
    asm volatile("ldmatrix.sync.aligned.m8n8.x4.shared.b16 {%0,%1,%2,%3}, [%4];"
                 : "=r"(r0), "=r"(r1), "=r"(r2), "=r"(r3) : "r"(addr));
}
__device__ __forceinline__ void ldsm_x4t(uint32_t& r0, uint32_t& r1, uint32_t& r2, uint32_t& r3,
                                         uint32_t addr) {
    asm volatile("ldmatrix.sync.aligned.m8n8.x4.trans.shared.b16 {%0,%1,%2,%3}, [%4];"
                 : "=r"(r0), "=r"(r1), "=r"(r2), "=r"(r3) : "r"(addr));
}

__device__ __forceinline__ void mma16816(float* d, const uint32_t* a, uint32_t b0, uint32_t b1) {
    asm volatile("mma.sync.aligned.m16n8k16.row.col.f32.bf16.bf16.f32 "
                 "{%0,%1,%2,%3}, {%4,%5,%6,%7}, {%8,%9}, {%0,%1,%2,%3};"
                 : "+f"(d[0]), "+f"(d[1]), "+f"(d[2]), "+f"(d[3])
                 : "r"(a[0]), "r"(a[1]), "r"(a[2]), "r"(a[3]), "r"(b0), "r"(b1));
}

__device__ __forceinline__ uint32_t packbf(float lo, float hi) {
    uint32_t r;
    asm("cvt.rn.bf16x2.f32 %0, %1, %2;" : "=r"(r) : "f"(hi), "f"(lo));
    return r;
}

// ---------------------------------------------------------------------------
// Conversion kernels (batched)
// ---------------------------------------------------------------------------
__global__ __launch_bounds__(256) void conv_act3(
    const float* __restrict__ Q, const float* __restrict__ K, const float* __restrict__ V,
    __nv_bfloat16* __restrict__ H, __nv_bfloat16* __restrict__ L)
{
    const int z = blockIdx.y;
    const float* A = (z == 0) ? Q : (z == 1) ? K : V;
    const size_t idx = ((size_t)blockIdx.x * 256 + threadIdx.x) * 8;
    const size_t oidx = (size_t)z*ASLOT + idx;
    float4 x0 = *(const float4*)(A + idx);
    float4 x1 = *(const float4*)(A + idx + 4);
    float x[8] = {x0.x,x0.y,x0.z,x0.w,x1.x,x1.y,x1.z,x1.w};
    alignas(16) __nv_bfloat16 h8[8];
    alignas(16) __nv_bfloat16 l8[8];
    #pragma unroll
    for (int j = 0; j < 8; j++) {
        __nv_bfloat16 hi = __float2bfloat16(x[j]);
        h8[j] = hi;
        l8[j] = __float2bfloat16(x[j] - __bfloat162float(hi));
    }
    *(uint4*)(H + oidx) = *(const uint4*)h8;
    *(uint4*)(L + oidx) = *(const uint4*)l8;
}

// W[k][n] fp32 -> Bt[n][k] bf16 hi/lo; z over 4 weights
__global__ __launch_bounds__(256) void conv_w4(
    const float* __restrict__ W0, const float* __restrict__ W1,
    const float* __restrict__ W2, const float* __restrict__ W3,
    __nv_bfloat16* __restrict__ H, __nv_bfloat16* __restrict__ L)
{
    __shared__ float t[64][65];
    const int z = blockIdx.z;
    const float* W = (z == 0) ? W0 : (z == 1) ? W1 : (z == 2) ? W2 : W3;
    const int c  = blockIdx.x;   // k block
    const int nj = blockIdx.y;   // n block

    #pragma unroll
    for (int it = 0; it < 4; it++) {
        const int idx = threadIdx.x + it*256;
        const int kr = idx >> 4;
        const int nc4 = (idx & 15)*4;
        float4 v = *(const float4*)&W[(size_t)(c*64 + kr)*1024 + nj*64 + nc4];
        t[kr][nc4+0] = v.x; t[kr][nc4+1] = v.y; t[kr][nc4+2] = v.z; t[kr][nc4+3] = v.w;
    }
    __syncthreads();

    #pragma unroll
    for (int it = 0; it < 2; it++) {
        const int item = threadIdx.x + it*256;
        const int r = item >> 3;
        const int g = item & 7;
        alignas(16) __nv_bfloat16 h8[8];
        alignas(16) __nv_bfloat16 l8[8];
        #pragma unroll
        for (int j = 0; j < 8; j++) {
            float x = t[g*8 + j][r];
            __nv_bfloat16 hi = __float2bfloat16(x);
            h8[j] = hi;
            l8[j] = __float2bfloat16(x - __bfloat162float(hi));
        }
        const size_t off = (size_t)z*WSLOT + (size_t)(nj*64 + r)*1024 + c*64 + g*8;
        *(uint4*)(H + off) = *(const uint4*)h8;
        *(uint4*)(L + off) = *(const uint4*)l8;
    }
}

// ---------------------------------------------------------------------------
// mma.sync bf16 GEMM, split-bf16 x3. CTA tile 128x128x32, 256 thr (8 warps,
// warp tile 32x64), 2-stage cp.async, 2 CTAs/SM. Batched over blockIdx.z.
// ---------------------------------------------------------------------------
#define GBM 128
#define GBN 128
#define GBK 32
#define G_PLANE  (128*40*2)                      // 10240 bytes: one hi or lo plane
#define G_STAGE  (4*G_PLANE)                     // 40960: Ah,Al,Bh,Bl
#define G_SMEM   (2*G_STAGE)                     // 81920

#define OFF_AH(s) ((s)*G_STAGE)
#define OFF_AL(s) ((s)*G_STAGE + G_PLANE)
#define OFF_BH(s) ((s)*G_STAGE + 2*G_PLANE)
#define OFF_BL(s) ((s)*G_STAGE + 3*G_PLANE)

__device__ __forceinline__ void g_load_stage(
    uint32_t sb, int s, int k0, int mbase, int nbase,
    const __nv_bfloat16* Ah, const __nv_bfloat16* Al,
    const __nv_bfloat16* Bh, const __nv_bfloat16* Bl, int tid)
{
    #pragma unroll
    for (int i = 0; i < 2; i++) {
        const int c = tid + i*256;          // 0..511
        const int row = c >> 2;
        const int kc  = (c & 3) * 8;
        const uint32_t d = sb + row*80 + kc*2;
        const size_t ga = (size_t)(mbase + row)*1024 + k0 + kc;
        cpa16(d + OFF_AH(s), Ah + ga);
        cpa16(d + OFF_AL(s), Al + ga);
        const size_t gb = (size_t)(nbase + row)*1024 + k0 + kc;
        cpa16(d + OFF_BH(s), Bh + gb);
        cpa16(d + OFF_BL(s), Bl + gb);
    }
}

__global__ __launch_bounds__(256, 2) void gemm_mma(
    const __nv_bfloat16* __restrict__ Ah, const __nv_bfloat16* __restrict__ Al,
    const __nv_bfloat16* __restrict__ Bh, const __nv_bfloat16* __restrict__ Bl,
    const float* __restrict__ bias0, const float* __restrict__ bias1,
    const float* __restrict__ bias2,
    float* __restrict__ C,
    __nv_bfloat16* __restrict__ Ch, __nv_bfloat16* __restrict__ Cl)
{
    extern __shared__ char smem[];
    const uint32_t sb = smem_u32(smem);
    const int tid = threadIdx.x;
    const int wid = tid >> 5;
    const int lid = tid & 31;
    const int warpM = (wid >> 1) * 32;     // 0,32,64,96
    const int warpN = (wid & 1) * 64;      // 0,64
    const int mbase = blockIdx.y * GBM;
    const int nbase = blockIdx.x * GBN;
    const int z = blockIdx.z;

    Ah += (size_t)z*ASLOT; Al += (size_t)z*ASLOT;
    Bh += (size_t)z*WSLOT; Bl += (size_t)z*WSLOT;
    const float* bias = (z == 0) ? bias0 : (z == 1) ? bias1 : bias2;

    float acc[2][8][4];
    #pragma unroll
    for (int m = 0; m < 2; m++)
        #pragma unroll
        for (int n = 0; n < 8; n++)
            #pragma unroll
            for (int r = 0; r < 4; r++) acc[m][n][r] = 0.0f;

    const int aRow  = warpM + (lid & 15);
    const int aKoff = (lid >> 4) * 8;
    const int bRow  = warpN + (lid & 7) + (lid >> 4)*8;
    const int bKoff = ((lid >> 3) & 1) * 8;

    g_load_stage(sb, 0, 0, mbase, nbase, Ah, Al, Bh, Bl, tid);
    CP_COMMIT();
    g_load_stage(sb, 1, GBK, mbase, nbase, Ah, Al, Bh, Bl, tid);
    CP_COMMIT();

    for (int it = 0; it < 32; it++) {
        const int s = it & 1;
        CP_WAIT1();
        __syncthreads();

        const uint32_t aBase = sb + OFF_AH(s) + aRow*80 + aKoff*2;
        const uint32_t alBase= sb + OFF_AL(s) + aRow*80 + aKoff*2;
        const uint32_t bBase = sb + OFF_BH(s) + bRow*80 + bKoff*2;
        const uint32_t blBase= sb + OFF_BL(s) + bRow*80 + bKoff*2;

        #pragma unroll
        for (int kk = 0; kk < 2; kk++) {
            const uint32_t kb = kk * 32;
            uint32_t bfr[8][2], ah2[2][4], al2[2][4];
            // B hi: 4 ldsm.x4 cover 8 n-frags
            #pragma unroll
            for (int p = 0; p < 4; p++) {
                uint32_t r0,r1,r2,r3;
                ldsm_x4(r0,r1,r2,r3, bBase + p*16*80 + kb);
                bfr[p*2+0][0]=r0; bfr[p*2+0][1]=r1; bfr[p*2+1][0]=r2; bfr[p*2+1][1]=r3;
            }
            #pragma unroll
            for (int m = 0; m < 2; m++) {
                ldsm_x4(ah2[m][0], ah2[m][1], ah2[m][2], ah2[m][3], aBase  + m*16*80 + kb);
                ldsm_x4(al2[m][0], al2[m][1], al2[m][2], al2[m][3], alBase + m*16*80 + kb);
            }
            #pragma unroll
            for (int m = 0; m < 2; m++)
                #pragma unroll
                for (int n = 0; n < 8; n++) {
                    mma16816(acc[m][n], ah2[m], bfr[n][0], bfr[n][1]);
                    mma16816(acc[m][n], al2[m], bfr[n][0], bfr[n][1]);
                }
            // B lo overwrites bfr
            #pragma unroll
            for (int p = 0; p < 4; p++) {
                uint32_t r0,r1,r2,r3;
                ldsm_x4(r0,r1,r2,r3, blBase + p*16*80 + kb);
                bfr[p*2+0][0]=r0; bfr[p*2+0][1]=r1; bfr[p*2+1][0]=r2; bfr[p*2+1][1]=r3;
            }
            #pragma unroll
            for (int m = 0; m < 2; m++)
                #pragma unroll
                for (int n = 0; n < 8; n++)
                    mma16816(acc[m][n], ah2[m], bfr[n][0], bfr[n][1]);
        }
        __syncthreads();
        if (it + 2 < 32)
            g_load_stage(sb, s, (it + 2)*GBK, mbase, nbase, Ah, Al, Bh, Bl, tid);
        CP_COMMIT();
    }

    // Epilogue
    const int r0base = mbase + warpM + (lid >> 2);
    const int cbase  = nbase + warpN + (lid & 3)*2;
    #pragma unroll
    for (int m = 0; m < 2; m++) {
        #pragma unroll
        for (int n = 0; n < 8; n++) {
            const int cc = cbase + n*8;
            const float2 bi = *(const float2*)&bias[cc];
            const int ra = r0base + m*16;
            float v0 = acc[m][n][0] + bi.x, v1 = acc[m][n][1] + bi.y;
            float v2 = acc[m][n][2] + bi.x, v3 = acc[m][n][3] + bi.y;
            if (C) {
                *(float2*)&C[(size_t)ra*1024 + cc] = make_float2(v0, v1);
                *(float2*)&C[(size_t)(ra + 8)*1024 + cc] = make_float2(v2, v3);
            } else {
                const size_t zo = (size_t)z*ASLOT;
                uint32_t h01 = packbf(v0, v1);
                uint32_t l01 = packbf(v0 - __uint_as_float(h01 << 16),
                                      v1 - __uint_as_float(h01 & 0xFFFF0000u));
                uint32_t h23 = packbf(v2, v3);
                uint32_t l23 = packbf(v2 - __uint_as_float(h23 << 16),
                                      v3 - __uint_as_float(h23 & 0xFFFF0000u));
                *(uint32_t*)&Ch[zo + (size_t)ra*1024 + cc] = h01;
                *(uint32_t*)&Cl[zo + (size_t)ra*1024 + cc] = l01;
                *(uint32_t*)&Ch[zo + (size_t)(ra + 8)*1024 + cc] = h23;
                *(uint32_t*)&Cl[zo + (size_t)(ra + 8)*1024 + cc] = l23;
            }
        }
    }
}

// ---------------------------------------------------------------------------
// Flash attention (causal), mma.sync split-bf16.
// Q-tile 128 rows, 256 thr (8 warps x 16 rows). Static-max softmax,
// deferred l reduction, Q fragments in registers. Smem 73728 B, 2 CTAs/SM.
// ---------------------------------------------------------------------------
#define FKT  9216                    // 64*144: one K/V hi/lo plane
#define FSTAGE (4*FKT)               // 36864 (Kh,Kl,Vh,Vl)
#define F_SMEM (2*FSTAGE)            // 73728
#define SM_SCALE 0.18033688f         // 0.125 * log2(e)

__global__ __launch_bounds__(256, 2) void flash_mma(
    const __nv_bfloat16* __restrict__ ph, const __nv_bfloat16* __restrict__ pl,
    __nv_bfloat16* __restrict__ oh, __nv_bfloat16* __restrict__ ol)
{
    extern __shared__ char smem[];
    const uint32_t sb = smem_u32(smem);
    const int tid = threadIdx.x;
    const int wid = tid >> 5;
    const int lid = tid & 31;
    const int qt  = (int)gridDim.x - 1 - (int)blockIdx.x;   // longest first
    const int bh_ = blockIdx.y;
    const int b = bh_ >> 4;
    const int h = bh_ & 15;
    const size_t base = (size_t)b * SS * DD + (size_t)h * DK;
    const __nv_bfloat16* qh = ph;
    const __nv_bfloat16* ql = pl;
    const __nv_bfloat16* kh = ph + ASLOT;
    const __nv_bfloat16* kl = pl + ASLOT;
    const __nv_bfloat16* vh = ph + 2*(size_t)ASLOT;
    const __nv_bfloat16* vl = pl + 2*(size_t)ASLOT;

    const int rowg0 = qt * 128;
    const int warpRow = wid * 16;
    const int nkt = 2*qt + 2;

    // Stage Q through KV buffer, load fragments into registers
    for (int i = tid; i < 1024; i += 256) {
        const int r = i >> 3, kc = (i & 7) * 8;
        const size_t g = base + (size_t)(rowg0 + r)*DD + kc;
        const uint32_t d = sb + r*144 + kc*2;
        cpa16(d, qh + g);
        cpa16(d + 128*144, ql + g);
    }
    CP_COMMIT();
    CP_WAIT0();
    __syncthreads();

    uint32_t qfh[4][4], qfl[4][4];
    {
        const uint32_t aAddr = sb + (warpRow + (lid & 15))*144 + ((lid >> 4)*8)*2;
        #pragma unroll
        for (int kk = 0; kk < 4; kk++) {
            ldsm_x4(qfh[kk][0], qfh[kk][1], qfh[kk][2], qfh[kk][3], aAddr + kk*32);
            ldsm_x4(qfl[kk][0], qfl[kk][1], qfl[kk][2], qfl[kk][3],
                    aAddr + 128*144 + kk*32);
        }
    }
    __syncthreads();

    #pragma unroll
    for (int s = 0; s < 2; s++) {
        const uint32_t st = sb + s*FSTAGE;
        for (int i = tid; i < 512; i += 256) {
            const int r = i >> 3, kc = (i & 7) * 8;
            const size_t g = base + (size_t)(s*64 + r)*DD + kc;
            const uint32_t d = st + r*144 + kc*2;
            cpa16(d,         kh + g);
            cpa16(d + FKT,   kl + g);
            cpa16(d + 2*FKT, vh + g);
            cpa16(d + 3*FKT, vl + g);
        }
        CP_COMMIT();
    }

    float oacc[8][4];
    #pragma unroll
    for (int t = 0; t < 8; t++)
        #pragma unroll
        for (int r = 0; r < 4; r++) oacc[t][r] = 0.0f;
    float l0 = 0.0f, l1 = 0.0f;

    const int row0 = warpRow + (lid >> 2);
    const int row1 = row0 + 8;
    const int colB = (lid & 3) * 2;

    for (int it = 0; it < nkt; it++) {
        CP_WAIT1();
        __syncthreads();
        const uint32_t st = sb + (it & 1)*FSTAGE;
        const bool active   = (it*64) <= (rowg0 + warpRow + 15);
        const bool needmask = (it*64 + 63) > (rowg0 + warpRow);

        if (active) {
            float sacc[8][4];
            #pragma unroll
            for (int t = 0; t < 8; t++)
                #pragma unroll
                for (int r = 0; r < 4; r++) sacc[t][r] = 0.0f;

            #pragma unroll
            for (int kk = 0; kk < 4; kk++) {
                const uint32_t kbase = st + ((lid & 7) + (lid >> 4)*8)*144
                                     + (((lid >> 3) & 1)*8 + kk*16)*2;
                #pragma unroll
                for (int p = 0; p < 4; p++) {
                    uint32_t h0,h1,h2,h3, x0,x1,x2,x3;
                    ldsm_x4(h0,h1,h2,h3, kbase + p*16*144);
                    ldsm_x4(x0,x1,x2,x3, kbase + FKT + p*16*144);
                    mma16816(sacc[2*p],   qfh[kk], h0, h1);
                    mma16816(sacc[2*p],   qfh[kk], x0, x1);
                    mma16816(sacc[2*p],   qfl[kk], h0, h1);
                    mma16816(sacc[2*p+1], qfh[kk], h2, h3);
                    mma16816(sacc[2*p+1], qfh[kk], x2, x3);
                    mma16816(sacc[2*p+1], qfl[kk], h2, h3);
                }
            }

            if (needmask) {
                #pragma unroll
                for (int t = 0; t < 8; t++) {
                    const int c0 = it*64 + t*8 + colB;
                    const int g0 = rowg0 + row0;
                    const int g1 = rowg0 + row1;
                    sacc[t][0] = (c0     > g0) ? -1.0e30f : sacc[t][0]*SM_SCALE;
                    sacc[t][1] = (c0 + 1 > g0) ? -1.0e30f : sacc[t][1]*SM_SCALE;
                    sacc[t][2] = (c0     > g1) ? -1.0e30f : sacc[t][2]*SM_SCALE;
                    sacc[t][3] = (c0 + 1 > g1) ? -1.0e30f : sacc[t][3]*SM_SCALE;
                }
            } else {
                #pragma unroll
                for (int t = 0; t < 8; t++)
                    #pragma unroll
                    for (int r = 0; r < 4; r++) sacc[t][r] *= SM_SCALE;
            }
            #pragma unroll
            for (int t = 0; t < 8; t++) {
                sacc[t][0] = exp2f(sacc[t][0]);
                sacc[t][1] = exp2f(sacc[t][1]);
                sacc[t][2] = exp2f(sacc[t][2]);
                sacc[t][3] = exp2f(sacc[t][3]);
                l0 += sacc[t][0] + sacc[t][1];
                l1 += sacc[t][2] + sacc[t][3];
            }

            #pragma unroll
            for (int kk = 0; kk < 4; kk++) {
                uint32_t ph4[4], pl4[4];
                #pragma unroll
                for (int u = 0; u < 2; u++) {
                    const int t = 2*kk + u;
                    uint32_t hA = packbf(sacc[t][0], sacc[t][1]);
                    uint32_t hB = packbf(sacc[t][2], sacc[t][3]);
                    ph4[2*u+0] = hA; ph4[2*u+1] = hB;
                    pl4[2*u+0] = packbf(sacc[t][0] - __uint_as_float(hA << 16),
                                        sacc[t][1] - __uint_as_float(hA & 0xFFFF0000u));
                    pl4[2*u+1] = packbf(sacc[t][2] - __uint_as_float(hB << 16),
                                        sacc[t][3] - __uint_as_float(hB & 0xFFFF0000u));
                }
                const uint32_t vbase = st + 2*FKT
                    + (kk*16 + (lid & 7) + ((lid >> 3) & 1)*8)*144 + ((lid >> 4)*8)*2;
                #pragma unroll
                for (int p = 0; p < 4; p++) {
                    uint32_t h0,h1,h2,h3, x0,x1,x2,x3;
                    ldsm_x4t(h0,h1,h2,h3, vbase + p*32);
                    ldsm_x4t(x0,x1,x2,x3, vbase + FKT + p*32);
                    mma16816(oacc[2*p],   ph4, h0, h1);
                    mma16816(oacc[2*p],   ph4, x0, x1);
                    mma16816(oacc[2*p],   pl4, h0, h1);
                    mma16816(oacc[2*p+1], ph4, h2, h3);
                    mma16816(oacc[2*p+1], ph4, x2, x3);
                    mma16816(oacc[2*p+1], pl4, h2, h3);
                }
            }
        }

        __syncthreads();
        if (it + 2 < nkt) {
            const uint32_t stn = sb + (it & 1)*FSTAGE;
            for (int i = tid; i < 512; i += 256) {
                const int r = i >> 3, kc = (i & 7) * 8;
                const size_t g = base + (size_t)((it + 2)*64 + r)*DD + kc;
                const uint32_t d = stn + r*144 + kc*2;
                cpa16(d,         kh + g);
                cpa16(d + FKT,   kl + g);
                cpa16(d + 2*FKT, vh + g);
                cpa16(d + 3*FKT, vl + g);
            }
        }
        CP_COMMIT();
    }

    // epilogue
    l0 += __shfl_xor_sync(0xffffffffu, l0, 1, 4);
    l0 += __shfl_xor_sync(0xffffffffu, l0, 2, 4);
    l1 += __shfl_xor_sync(0xffffffffu, l1, 1, 4);
    l1 += __shfl_xor_sync(0xffffffffu, l1, 2, 4);
    const float il0 = 1.0f / l0, il1 = 1.0f / l1;
    const size_t ga0 = base + (size_t)(rowg0 + row0)*DD + colB;
    const size_t ga1 = base + (size_t)(rowg0 + row1)*DD + colB;
    #pragma unroll
    for (int t = 0; t < 8; t++) {
        const float v0 = oacc[t][0]*il0, v1 = oacc[t][1]*il0;
        const float v2 = oacc[t][2]*il1, v3 = oacc[t][3]*il1;
        uint32_t h01 = packbf(v0, v1);
        uint32_t l01 = packbf(v0 - __uint_as_float(h01 << 16),
                              v1 - __uint_as_float(h01 & 0xFFFF0000u));
        uint32_t h23 = packbf(v2, v3);
        uint32_t l23 = packbf(v2 - __uint_as_float(h23 << 16),
                              v3 - __uint_as_float(h23 & 0xFFFF0000u));
        *(uint32_t*)&oh[ga0 + t*8] = h01;
        *(uint32_t*)&ol[ga0 + t*8] = l01;
        *(uint32_t*)&oh[ga1 + t*8] = h23;
        *(uint32_t*)&ol[ga1 + t*8] = l23;
    }
}

// ---------------------------------------------------------------------------
// Launch
// ---------------------------------------------------------------------------
extern "C" void kernel_launch(void* const* d_in, const int* in_sizes, int n_in,
                              void* d_out, int out_size)
{
    const float* Q   = (const float*)d_in[0];
    const float* K   = (const float*)d_in[1];
    const float* V   = (const float*)d_in[2];
    const float* W_q = (const float*)d_in[3];
    const float* b_q = (const float*)d_in[4];
    const float* W_k = (const float*)d_in[5];
    const float* b_k = (const float*)d_in[6];
    const float* W_v = (const float*)d_in[7];
    const float* b_v = (const float*)d_in[8];
    const float* W_o = (const float*)d_in[9];
    const float* b_o = (const float*)d_in[10];
    float* out = (float*)d_out;

    __nv_bfloat16 *xh, *xl, *ph, *pl, *oh, *ol, *bh, *bl;
    cudaGetSymbolAddress((void**)&xh, g_xh);
    cudaGetSymbolAddress((void**)&xl, g_xl);
    cudaGetSymbolAddress((void**)&ph, g_ph);
    cudaGetSymbolAddress((void**)&pl, g_pl);
    cudaGetSymbolAddress((void**)&oh, g_oh);
    cudaGetSymbolAddress((void**)&ol, g_ol);
    cudaGetSymbolAddress((void**)&bh, g_bh);
    cudaGetSymbolAddress((void**)&bl, g_bl);

    cudaFuncSetAttribute(gemm_mma, cudaFuncAttributeMaxDynamicSharedMemorySize, G_SMEM);
    cudaFuncSetAttribute(flash_mma, cudaFuncAttributeMaxDynamicSharedMemorySize, F_SMEM);

    dim3 cwGrid(16, 16, 4);
    conv_w4<<<cwGrid, 256>>>(W_q, W_k, W_v, W_o, bh, bl);
    dim3 caGrid(2048, 3);
    conv_act3<<<caGrid, 256>>>(Q, K, V, xh, xl);

    dim3 gGrid3(DD/GBN, MROWS/GBM, 3);   // (8,32,3) = 768 CTAs
    gemm_mma<<<gGrid3, 256, G_SMEM>>>(xh, xl, bh, bl, b_q, b_k, b_v,
                                      nullptr, ph, pl);

    dim3 fGrid(SS/128, BB*HH);           // (16, 32)
    flash_mma<<<fGrid, 256, F_SMEM>>>(ph, pl, oh, ol);

    dim3 gGrid1(DD/GBN, MROWS/GBM, 1);
    gemm_mma<<<gGrid1, 256, G_SMEM>>>(oh, ol, bh + 3*(size_t)WSLOT, bl + 3*(size_t)WSLOT,
                                      b_o, nullptr, nullptr, out, nullptr, nullptr);
}

// round 9
// speedup vs baseline: 1.0191x; 1.0191x over previous
#include <cuda_runtime.h>
#include <cuda_bf16.h>
#include <cstdint>
#include <cstddef>

// Problem constants
#define BB   2
#define SS   2048
#define DD   1024
#define HH   16
#define DK   64
#define MROWS (BB*SS)          // 4096
#define ASLOT (MROWS*DD)       // 4M elements
#define WSLOT (DD*DD)          // 1M elements

// ---------------------------------------------------------------------------
// Scratch (__device__ globals; allocation-free rule)
// ---------------------------------------------------------------------------
__device__ __nv_bfloat16 g_xh[3*ASLOT];    // activation hi (Q,K,V inputs)
__device__ __nv_bfloat16 g_xl[3*ASLOT];
__device__ __nv_bfloat16 g_ph[3*ASLOT];    // projected q,k,v hi
__device__ __nv_bfloat16 g_pl[3*ASLOT];
__device__ __nv_bfloat16 g_oh[ASLOT];      // attention out hi
__device__ __nv_bfloat16 g_ol[ASLOT];
__device__ __nv_bfloat16 g_bh[4*WSLOT];    // W^T hi [n][k], 4 weights
__device__ __nv_bfloat16 g_bl[4*WSLOT];

// ---------------------------------------------------------------------------
// PTX helpers (base sm_103-safe: cp.async, ldmatrix, mma.sync only)
// ---------------------------------------------------------------------------
__device__ __forceinline__ uint32_t smem_u32(const void* p) {
    return (uint32_t)__cvta_generic_to_shared(p);
}

__device__ __forceinline__ void cpa16(uint32_t dst, const void* src) {
    asm volatile("cp.async.cg.shared.global [%0], [%1], 16;" :: "r"(dst), "l"(src) : "memory");
}
#define CP_COMMIT() asm volatile("cp.async.commit_group;" ::: "memory")
#define CP_WAIT0()  asm volatile("cp.async.wait_group 0;" ::: "memory")
#define CP_WAIT1()  asm volatile("cp.async.wait_group 1;" ::: "memory")

__device__ __forceinline__ void ldsm_x4(uint32_t& r0, uint32_t& r1, uint32_t& r2, uint32_t& r3,
                                        uint32_t addr) {
    asm volatile("ldmatrix.sync.aligned.m8n8.x4.shared.b16 {%0,%1,%2,%3}, [%4];"
                 : "=r"(r0), "=r"(r1), "=r"(r2), "=r"(r3) : "r"(addr));
}
__device__ __forceinline__ void ldsm_x4t(uint32_t& r0, uint32_t& r1, uint32_t& r2, uint32_t& r3,
                                         uint32_t addr) {
    asm volatile("ldmatrix.sync.aligned.m8n8.x4.trans.shared.b16 {%0,%1,%2,%3}, [%4];"
                 : "=r"(r0), "=r"(r1), "=r"(r2), "=r"(r3) : "r"(addr));
}

__device__ __forceinline__ void mma16816(float* d, const uint32_t* a, uint32_t b0, uint32_t b1) {
    asm volatile("mma.sync.aligned.m16n8k16.row.col.f32.bf16.bf16.f32 "
                 "{%0,%1,%2,%3}, {%4,%5,%6,%7}, {%8,%9}, {%0,%1,%2,%3};"
                 : "+f"(d[0]), "+f"(d[1]), "+f"(d[2]), "+f"(d[3])
                 : "r"(a[0]), "r"(a[1]), "r"(a[2]), "r"(a[3]), "r"(b0), "r"(b1));
}

__device__ __forceinline__ uint32_t packbf(float lo, float hi) {
    uint32_t r;
    asm("cvt.rn.bf16x2.f32 %0, %1, %2;" : "=r"(r) : "f"(hi), "f"(lo));
    return r;
}

// ---------------------------------------------------------------------------
// Conversion kernels (batched)
// ---------------------------------------------------------------------------
__global__ __launch_bounds__(256) void conv_act3(
    const float* __restrict__ Q, const float* __restrict__ K, const float* __restrict__ V,
    __nv_bfloat16* __restrict__ H, __nv_bfloat16* __restrict__ L)
{
    const int z = blockIdx.y;
    const float* A = (z == 0) ? Q : (z == 1) ? K : V;
    const size_t idx = ((size_t)blockIdx.x * 256 + threadIdx.x) * 8;
    const size_t oidx = (size_t)z*ASLOT + idx;
    float4 x0 = *(const float4*)(A + idx);
    float4 x1 = *(const float4*)(A + idx + 4);
    float x[8] = {x0.x,x0.y,x0.z,x0.w,x1.x,x1.y,x1.z,x1.w};
    alignas(16) __nv_bfloat16 h8[8];
    alignas(16) __nv_bfloat16 l8[8];
    #pragma unroll
    for (int j = 0; j < 8; j++) {
        __nv_bfloat16 hi = __float2bfloat16(x[j]);
        h8[j] = hi;
        l8[j] = __float2bfloat16(x[j] - __bfloat162float(hi));
    }
    *(uint4*)(H + oidx) = *(const uint4*)h8;
    *(uint4*)(L + oidx) = *(const uint4*)l8;
}

// W[k][n] fp32 -> Bt[n][k] bf16 hi/lo; z over 4 weights
__global__ __launch_bounds__(256) void conv_w4(
    const float* __restrict__ W0, const float* __restrict__ W1,
    const float* __restrict__ W2, const float* __restrict__ W3,
    __nv_bfloat16* __restrict__ H, __nv_bfloat16* __restrict__ L)
{
    __shared__ float t[64][65];
    const int z = blockIdx.z;
    const float* W = (z == 0) ? W0 : (z == 1) ? W1 : (z == 2) ? W2 : W3;
    const int c  = blockIdx.x;   // k block
    const int nj = blockIdx.y;   // n block

    #pragma unroll
    for (int it = 0; it < 4; it++) {
        const int idx = threadIdx.x + it*256;
        const int kr = idx >> 4;
        const int nc4 = (idx & 15)*4;
        float4 v = *(const float4*)&W[(size_t)(c*64 + kr)*1024 + nj*64 + nc4];
        t[kr][nc4+0] = v.x; t[kr][nc4+1] = v.y; t[kr][nc4+2] = v.z; t[kr][nc4+3] = v.w;
    }
    __syncthreads();

    #pragma unroll
    for (int it = 0; it < 2; it++) {
        const int item = threadIdx.x + it*256;
        const int r = item >> 3;
        const int g = item & 7;
        alignas(16) __nv_bfloat16 h8[8];
        alignas(16) __nv_bfloat16 l8[8];
        #pragma unroll
        for (int j = 0; j < 8; j++) {
            float x = t[g*8 + j][r];
            __nv_bfloat16 hi = __float2bfloat16(x);
            h8[j] = hi;
            l8[j] = __float2bfloat16(x - __bfloat162float(hi));
        }
        const size_t off = (size_t)z*WSLOT + (size_t)(nj*64 + r)*1024 + c*64 + g*8;
        *(uint4*)(H + off) = *(const uint4*)h8;
        *(uint4*)(L + off) = *(const uint4*)l8;
    }
}

// ---------------------------------------------------------------------------
// mma.sync bf16 GEMM, split-bf16 x3. CTA 256x128x32, 512 thr, 3-stage
// cp.async with load-at-top (prefetch overlaps 2 mma iterations).
// Batched over blockIdx.z.
// ---------------------------------------------------------------------------
#define GBM 256
#define GBN 128
#define GBK 32
#define G_A_BYTES (GBM*40*2)
#define G_B_BYTES (GBN*40*2)
#define G_STAGE   (2*G_A_BYTES + 2*G_B_BYTES)    // 61440
#define G_SMEM    (3*G_STAGE)                    // 184320

#define OFF_AH(s) ((s)*G_STAGE)
#define OFF_AL(s) ((s)*G_STAGE + G_A_BYTES)
#define OFF_BH(s) ((s)*G_STAGE + 2*G_A_BYTES)
#define OFF_BL(s) ((s)*G_STAGE + 2*G_A_BYTES + G_B_BYTES)

__device__ __forceinline__ void g_load_stage(
    uint32_t sb, int s, int k0, int mbase, int nbase,
    const __nv_bfloat16* Ah, const __nv_bfloat16* Al,
    const __nv_bfloat16* Bh, const __nv_bfloat16* Bl, int tid)
{
    #pragma unroll
    for (int i = 0; i < 2; i++) {
        const int c = tid + i*512;
        const int row = c >> 2;
        const int kc  = (c & 3) * 8;
        const size_t g = (size_t)(mbase + row)*1024 + k0 + kc;
        const uint32_t d = sb + row*80 + kc*2;
        cpa16(d + OFF_AH(s), Ah + g);
        cpa16(d + OFF_AL(s), Al + g);
    }
    {
        const int row = tid >> 2;
        const int kc  = (tid & 3) * 8;
        const size_t g = (size_t)(nbase + row)*1024 + k0 + kc;
        const uint32_t d = sb + row*80 + kc*2;
        cpa16(d + OFF_BH(s), Bh + g);
        cpa16(d + OFF_BL(s), Bl + g);
    }
}

__global__ __launch_bounds__(512, 1) void gemm_mma(
    const __nv_bfloat16* __restrict__ Ah, const __nv_bfloat16* __restrict__ Al,
    const __nv_bfloat16* __restrict__ Bh, const __nv_bfloat16* __restrict__ Bl,
    const float* __restrict__ bias0, const float* __restrict__ bias1,
    const float* __restrict__ bias2,
    float* __restrict__ C,
    __nv_bfloat16* __restrict__ Ch, __nv_bfloat16* __restrict__ Cl)
{
    extern __shared__ char smem[];
    const uint32_t sb = smem_u32(smem);
    const int tid = threadIdx.x;
    const int wid = tid >> 5;
    const int lid = tid & 31;
    const int warpM = (wid >> 2) * 64;
    const int warpN = (wid & 3) * 32;
    const int mbase = blockIdx.y * GBM;
    const int nbase = blockIdx.x * GBN;
    const int z = blockIdx.z;

    Ah += (size_t)z*ASLOT; Al += (size_t)z*ASLOT;
    Bh += (size_t)z*WSLOT; Bl += (size_t)z*WSLOT;
    const float* bias = (z == 0) ? bias0 : (z == 1) ? bias1 : bias2;

    float acc[4][4][4];
    #pragma unroll
    for (int m = 0; m < 4; m++)
        #pragma unroll
        for (int n = 0; n < 4; n++)
            #pragma unroll
            for (int r = 0; r < 4; r++) acc[m][n][r] = 0.0f;

    const int aRow  = warpM + (lid & 15);
    const int aKoff = (lid >> 4) * 8;
    const int bRow  = warpN + (lid & 7) + (lid >> 4)*8;
    const int bKoff = ((lid >> 3) & 1) * 8;

    g_load_stage(sb, 0, 0, mbase, nbase, Ah, Al, Bh, Bl, tid);
    CP_COMMIT();
    g_load_stage(sb, 1, GBK, mbase, nbase, Ah, Al, Bh, Bl, tid);
    CP_COMMIT();

    int s = 0, sn = 2;   // current stage, stage to prefetch into
    for (int it = 0; it < 32; it++) {
        CP_WAIT1();
        __syncthreads();

        // prefetch (it+2) at TOP: overlaps with this iteration's mma work
        if (it + 2 < 32)
            g_load_stage(sb, sn, (it + 2)*GBK, mbase, nbase, Ah, Al, Bh, Bl, tid);
        CP_COMMIT();

        const uint32_t aBase = sb + OFF_AH(s) + aRow*80 + aKoff*2;
        const uint32_t alBase= sb + OFF_AL(s) + aRow*80 + aKoff*2;
        const uint32_t bBase = sb + OFF_BH(s) + bRow*80 + bKoff*2;
        const uint32_t blBase= sb + OFF_BL(s) + bRow*80 + bKoff*2;

        #pragma unroll
        for (int kk = 0; kk < 2; kk++) {
            const uint32_t kb = kk * 32;
            uint32_t af[4][4], bh2[4][2], bl2[4][2];
            #pragma unroll
            for (int p = 0; p < 2; p++) {
                uint32_t r0,r1,r2,r3;
                ldsm_x4(r0,r1,r2,r3, bBase + p*16*80 + kb);
                bh2[p*2+0][0]=r0; bh2[p*2+0][1]=r1; bh2[p*2+1][0]=r2; bh2[p*2+1][1]=r3;
                ldsm_x4(r0,r1,r2,r3, blBase + p*16*80 + kb);
                bl2[p*2+0][0]=r0; bl2[p*2+0][1]=r1; bl2[p*2+1][0]=r2; bl2[p*2+1][1]=r3;
            }
            #pragma unroll
            for (int m = 0; m < 4; m++)
                ldsm_x4(af[m][0], af[m][1], af[m][2], af[m][3], aBase + m*16*80 + kb);
            #pragma unroll
            for (int m = 0; m < 4; m++)
                #pragma unroll
                for (int n = 0; n < 4; n++) {
                    mma16816(acc[m][n], af[m], bh2[n][0], bh2[n][1]);
                    mma16816(acc[m][n], af[m], bl2[n][0], bl2[n][1]);
                }
            #pragma unroll
            for (int m = 0; m < 4; m++)
                ldsm_x4(af[m][0], af[m][1], af[m][2], af[m][3], alBase + m*16*80 + kb);
            #pragma unroll
            for (int m = 0; m < 4; m++)
                #pragma unroll
                for (int n = 0; n < 4; n++)
                    mma16816(acc[m][n], af[m], bh2[n][0], bh2[n][1]);
        }
        s  = (s  == 2) ? 0 : s  + 1;
        sn = (sn == 2) ? 0 : sn + 1;
    }

    // Epilogue
    const int r0base = mbase + warpM + (lid >> 2);
    const int cbase  = nbase + warpN + (lid & 3)*2;
    #pragma unroll
    for (int m = 0; m < 4; m++) {
        #pragma unroll
        for (int n = 0; n < 4; n++) {
            const int cc = cbase + n*8;
            const float2 bi = *(const float2*)&bias[cc];
            const int ra = r0base + m*16;
            float v0 = acc[m][n][0] + bi.x, v1 = acc[m][n][1] + bi.y;
            float v2 = acc[m][n][2] + bi.x, v3 = acc[m][n][3] + bi.y;
            if (C) {
                *(float2*)&C[(size_t)ra*1024 + cc] = make_float2(v0, v1);
                *(float2*)&C[(size_t)(ra + 8)*1024 + cc] = make_float2(v2, v3);
            } else {
                const size_t zo = (size_t)z*ASLOT;
                uint32_t h01 = packbf(v0, v1);
                uint32_t l01 = packbf(v0 - __uint_as_float(h01 << 16),
                                      v1 - __uint_as_float(h01 & 0xFFFF0000u));
                uint32_t h23 = packbf(v2, v3);
                uint32_t l23 = packbf(v2 - __uint_as_float(h23 << 16),
                                      v3 - __uint_as_float(h23 & 0xFFFF0000u));
                *(uint32_t*)&Ch[zo + (size_t)ra*1024 + cc] = h01;
                *(uint32_t*)&Cl[zo + (size_t)ra*1024 + cc] = l01;
                *(uint32_t*)&Ch[zo + (size_t)(ra + 8)*1024 + cc] = h23;
                *(uint32_t*)&Cl[zo + (size_t)(ra + 8)*1024 + cc] = l23;
            }
        }
    }
}

// ---------------------------------------------------------------------------
// Flash attention (causal), mma.sync split-bf16.
// Q-tile 128 rows, 256 thr (8 warps x 16 rows). Static-max softmax,
// deferred l reduction, Q fragments in registers.
// 3-stage KV pipeline with load-at-top; smem 110592 B, 2 CTAs/SM.
// ---------------------------------------------------------------------------
#define FKT  9216                    // 64*144: one K/V hi/lo plane
#define FSTAGE (4*FKT)               // 36864 (Kh,Kl,Vh,Vl)
#define F_SMEM (3*FSTAGE)            // 110592
#define SM_SCALE 0.18033688f         // 0.125 * log2(e)

__global__ __launch_bounds__(256, 2) void flash_mma(
    const __nv_bfloat16* __restrict__ ph, const __nv_bfloat16* __restrict__ pl,
    __nv_bfloat16* __restrict__ oh, __nv_bfloat16* __restrict__ ol)
{
    extern __shared__ char smem[];
    const uint32_t sb = smem_u32(smem);
    const int tid = threadIdx.x;
    const int wid = tid >> 5;
    const int lid = tid & 31;
    const int qt  = (int)gridDim.x - 1 - (int)blockIdx.x;   // longest first
    const int bh_ = blockIdx.y;
    const int b = bh_ >> 4;
    const int h = bh_ & 15;
    const size_t base = (size_t)b * SS * DD + (size_t)h * DK;
    const __nv_bfloat16* qh = ph;
    const __nv_bfloat16* ql = pl;
    const __nv_bfloat16* kh = ph + ASLOT;
    const __nv_bfloat16* kl = pl + ASLOT;
    const __nv_bfloat16* vh = ph + 2*(size_t)ASLOT;
    const __nv_bfloat16* vl = pl + 2*(size_t)ASLOT;

    const int rowg0 = qt * 128;
    const int warpRow = wid * 16;
    const int nkt = 2*qt + 2;

    // Stage Q through smem (stage-0 region), load fragments into registers
    for (int i = tid; i < 1024; i += 256) {
        const int r = i >> 3, kc = (i & 7) * 8;
        const size_t g = base + (size_t)(rowg0 + r)*DD + kc;
        const uint32_t d = sb + r*144 + kc*2;
        cpa16(d, qh + g);
        cpa16(d + 128*144, ql + g);
    }
    CP_COMMIT();
    CP_WAIT0();
    __syncthreads();

    uint32_t qfh[4][4], qfl[4][4];
    {
        const uint32_t aAddr = sb + (warpRow + (lid & 15))*144 + ((lid >> 4)*8)*2;
        #pragma unroll
        for (int kk = 0; kk < 4; kk++) {
            ldsm_x4(qfh[kk][0], qfh[kk][1], qfh[kk][2], qfh[kk][3], aAddr + kk*32);
            ldsm_x4(qfl[kk][0], qfl[kk][1], qfl[kk][2], qfl[kk][3],
                    aAddr + 128*144 + kk*32);
        }
    }
    __syncthreads();

    // KV prologue: stages 0 and 1
    #pragma unroll
    for (int sp = 0; sp < 2; sp++) {
        const uint32_t st = sb + sp*FSTAGE;
        for (int i = tid; i < 512; i += 256) {
            const int r = i >> 3, kc = (i & 7) * 8;
            const size_t g = base + (size_t)(sp*64 + r)*DD + kc;
            const uint32_t d = st + r*144 + kc*2;
            cpa16(d,         kh + g);
            cpa16(d + FKT,   kl + g);
            cpa16(d + 2*FKT, vh + g);
            cpa16(d + 3*FKT, vl + g);
        }
        CP_COMMIT();
    }

    float oacc[8][4];
    #pragma unroll
    for (int t = 0; t < 8; t++)
        #pragma unroll
        for (int r = 0; r < 4; r++) oacc[t][r] = 0.0f;
    float l0 = 0.0f, l1 = 0.0f;

    const int row0 = warpRow + (lid >> 2);
    const int row1 = row0 + 8;
    const int colB = (lid & 3) * 2;

    int s = 0, sn = 2;
    for (int it = 0; it < nkt; it++) {
        CP_WAIT1();
        __syncthreads();

        // prefetch (it+2) at TOP
        if (it + 2 < nkt) {
            const uint32_t stn = sb + sn*FSTAGE;
            for (int i = tid; i < 512; i += 256) {
                const int r = i >> 3, kc = (i & 7) * 8;
                const size_t g = base + (size_t)((it + 2)*64 + r)*DD + kc;
                const uint32_t d = stn + r*144 + kc*2;
                cpa16(d,         kh + g);
                cpa16(d + FKT,   kl + g);
                cpa16(d + 2*FKT, vh + g);
                cpa16(d + 3*FKT, vl + g);
            }
        }
        CP_COMMIT();

        const uint32_t st = sb + s*FSTAGE;
        const bool active   = (it*64) <= (rowg0 + warpRow + 15);
        const bool needmask = (it*64 + 63) > (rowg0 + warpRow);

        if (active) {
            float sacc[8][4];
            #pragma unroll
            for (int t = 0; t < 8; t++)
                #pragma unroll
                for (int r = 0; r < 4; r++) sacc[t][r] = 0.0f;

            #pragma unroll
            for (int kk = 0; kk < 4; kk++) {
                const uint32_t kbase = st + ((lid & 7) + (lid >> 4)*8)*144
                                     + (((lid >> 3) & 1)*8 + kk*16)*2;
                #pragma unroll
                for (int p = 0; p < 4; p++) {
                    uint32_t h0,h1,h2,h3, x0,x1,x2,x3;
                    ldsm_x4(h0,h1,h2,h3, kbase + p*16*144);
                    ldsm_x4(x0,x1,x2,x3, kbase + FKT + p*16*144);
                    mma16816(sacc[2*p],   qfh[kk], h0, h1);
                    mma16816(sacc[2*p],   qfh[kk], x0, x1);
                    mma16816(sacc[2*p],   qfl[kk], h0, h1);
                    mma16816(sacc[2*p+1], qfh[kk], h2, h3);
                    mma16816(sacc[2*p+1], qfh[kk], x2, x3);
                    mma16816(sacc[2*p+1], qfl[kk], h2, h3);
                }
            }

            if (needmask) {
                #pragma unroll
                for (int t = 0; t < 8; t++) {
                    const int c0 = it*64 + t*8 + colB;
                    const int g0 = rowg0 + row0;
                    const int g1 = rowg0 + row1;
                    sacc[t][0] = (c0     > g0) ? -1.0e30f : sacc[t][0]*SM_SCALE;
                    sacc[t][1] = (c0 + 1 > g0) ? -1.0e30f : sacc[t][1]*SM_SCALE;
                    sacc[t][2] = (c0     > g1) ? -1.0e30f : sacc[t][2]*SM_SCALE;
                    sacc[t][3] = (c0 + 1 > g1) ? -1.0e30f : sacc[t][3]*SM_SCALE;
                }
            } else {
                #pragma unroll
                for (int t = 0; t < 8; t++)
                    #pragma unroll
                    for (int r = 0; r < 4; r++) sacc[t][r] *= SM_SCALE;
            }
            #pragma unroll
            for (int t = 0; t < 8; t++) {
                sacc[t][0] = exp2f(sacc[t][0]);
                sacc[t][1] = exp2f(sacc[t][1]);
                sacc[t][2] = exp2f(sacc[t][2]);
                sacc[t][3] = exp2f(sacc[t][3]);
                l0 += sacc[t][0] + sacc[t][1];
                l1 += sacc[t][2] + sacc[t][3];
            }

            #pragma unroll
            for (int kk = 0; kk < 4; kk++) {
                uint32_t ph4[4], pl4[4];
                #pragma unroll
                for (int u = 0; u < 2; u++) {
                    const int t = 2*kk + u;
                    uint32_t hA = packbf(sacc[t][0], sacc[t][1]);
                    uint32_t hB = packbf(sacc[t][2], sacc[t][3]);
                    ph4[2*u+0] = hA; ph4[2*u+1] = hB;
                    pl4[2*u+0] = packbf(sacc[t][0] - __uint_as_float(hA << 16),
                                        sacc[t][1] - __uint_as_float(hA & 0xFFFF0000u));
                    pl4[2*u+1] = packbf(sacc[t][2] - __uint_as_float(hB << 16),
                                        sacc[t][3] - __uint_as_float(hB & 0xFFFF0000u));
                }
                const uint32_t vbase = st + 2*FKT
                    + (kk*16 + (lid & 7) + ((lid >> 3) & 1)*8)*144 + ((lid >> 4)*8)*2;
                #pragma unroll
                for (int p = 0; p < 4; p++) {
                    uint32_t h0,h1,h2,h3, x0,x1,x2,x3;
                    ldsm_x4t(h0,h1,h2,h3, vbase + p*32);
                    ldsm_x4t(x0,x1,x2,x3, vbase + FKT + p*32);
                    mma16816(oacc[2*p],   ph4, h0, h1);
                    mma16816(oacc[2*p],   ph4, x0, x1);
                    mma16816(oacc[2*p],   pl4, h0, h1);
                    mma16816(oacc[2*p+1], ph4, h2, h3);
                    mma16816(oacc[2*p+1], ph4, x2, x3);
                    mma16816(oacc[2*p+1], pl4, h2, h3);
                }
            }
        }
        s  = (s  == 2) ? 0 : s  + 1;
        sn = (sn == 2) ? 0 : sn + 1;
    }

    // epilogue
    l0 += __shfl_xor_sync(0xffffffffu, l0, 1, 4);
    l0 += __shfl_xor_sync(0xffffffffu, l0, 2, 4);
    l1 += __shfl_xor_sync(0xffffffffu, l1, 1, 4);
    l1 += __shfl_xor_sync(0xffffffffu, l1, 2, 4);
    const float il0 = 1.0f / l0, il1 = 1.0f / l1;
    const size_t ga0 = base + (size_t)(rowg0 + row0)*DD + colB;
    const size_t ga1 = base + (size_t)(rowg0 + row1)*DD + colB;
    #pragma unroll
    for (int t = 0; t < 8; t++) {
        const float v0 = oacc[t][0]*il0, v1 = oacc[t][1]*il0;
        const float v2 = oacc[t][2]*il1, v3 = oacc[t][3]*il1;
        uint32_t h01 = packbf(v0, v1);
        uint32_t l01 = packbf(v0 - __uint_as_float(h01 << 16),
                              v1 - __uint_as_float(h01 & 0xFFFF0000u));
        uint32_t h23 = packbf(v2, v3);
        uint32_t l23 = packbf(v2 - __uint_as_float(h23 << 16),
                              v3 - __uint_as_float(h23 & 0xFFFF0000u));
        *(uint32_t*)&oh[ga0 + t*8] = h01;
        *(uint32_t*)&ol[ga0 + t*8] = l01;
        *(uint32_t*)&oh[ga1 + t*8] = h23;
        *(uint32_t*)&ol[ga1 + t*8] = l23;
    }
}

// ---------------------------------------------------------------------------
// Launch
// ---------------------------------------------------------------------------
extern "C" void kernel_launch(void* const* d_in, const int* in_sizes, int n_in,
                              void* d_out, int out_size)
{
    const float* Q   = (const float*)d_in[0];
    const float* K   = (const float*)d_in[1];
    const float* V   = (const float*)d_in[2];
    const float* W_q = (const float*)d_in[3];
    const float* b_q = (const float*)d_in[4];
    const float* W_k = (const float*)d_in[5];
    const float* b_k = (const float*)d_in[6];
    const float* W_v = (const float*)d_in[7];
    const float* b_v = (const float*)d_in[8];
    const float* W_o = (const float*)d_in[9];
    const float* b_o = (const float*)d_in[10];
    float* out = (float*)d_out;

    __nv_bfloat16 *xh, *xl, *ph, *pl, *oh, *ol, *bh, *bl;
    cudaGetSymbolAddress((void**)&xh, g_xh);
    cudaGetSymbolAddress((void**)&xl, g_xl);
    cudaGetSymbolAddress((void**)&ph, g_ph);
    cudaGetSymbolAddress((void**)&pl, g_pl);
    cudaGetSymbolAddress((void**)&oh, g_oh);
    cudaGetSymbolAddress((void**)&ol, g_ol);
    cudaGetSymbolAddress((void**)&bh, g_bh);
    cudaGetSymbolAddress((void**)&bl, g_bl);

    cudaFuncSetAttribute(gemm_mma, cudaFuncAttributeMaxDynamicSharedMemorySize, G_SMEM);
    cudaFuncSetAttribute(flash_mma, cudaFuncAttributeMaxDynamicSharedMemorySize, F_SMEM);

    dim3 cwGrid(16, 16, 4);
    conv_w4<<<cwGrid, 256>>>(W_q, W_k, W_v, W_o, bh, bl);
    dim3 caGrid(2048, 3);
    conv_act3<<<caGrid, 256>>>(Q, K, V, xh, xl);

    dim3 gGrid3(DD/GBN, MROWS/GBM, 3);   // (8,16,3)
    gemm_mma<<<gGrid3, 512, G_SMEM>>>(xh, xl, bh, bl, b_q, b_k, b_v,
                                      nullptr, ph, pl);

    dim3 fGrid(SS/128, BB*HH);           // (16, 32)
    flash_mma<<<fGrid, 256, F_SMEM>>>(ph, pl, oh, ol);

    dim3 gGrid1(DD/GBN, MROWS/GBM, 1);
    gemm_mma<<<gGrid1, 512, G_SMEM>>>(oh, ol, bh + 3*(size_t)WSLOT, bl + 3*(size_t)WSLOT,
                                      b_o, nullptr, nullptr, out, nullptr, nullptr);
}

// round 10
// speedup vs baseline: 1.3880x; 1.3621x over previous
#include <cuda_runtime.h>
#include <cuda_fp16.h>
#include <cstdint>
#include <cstddef>

// Problem constants
#define BB   2
#define SS   2048
#define DD   1024
#define HH   16
#define DK   64
#define MROWS (BB*SS)          // 4096
#define ASLOT (MROWS*DD)       // 4M elements
#define WSLOT (DD*DD)          // 1M elements

// ---------------------------------------------------------------------------
// Scratch (__device__ globals; allocation-free rule)
// ---------------------------------------------------------------------------
__device__ __half g_xh[3*ASLOT];    // activation hi (Q,K,V inputs)
__device__ __half g_xl[3*ASLOT];    // activation lo
__device__ __half g_ph[3*ASLOT];    // projected q,k,v hi
__device__ __half g_pl[3*ASLOT];    // projected q,k,v lo (only q's used)
__device__ __half g_oh[ASLOT];      // attention out hi
__device__ __half g_ol[ASLOT];      // attention out lo
__device__ __half g_bh[4*WSLOT];    // W^T [n][k] fp16, 4 weights (single prec)

// ---------------------------------------------------------------------------
// PTX helpers (base sm_103-safe: cp.async, ldmatrix, mma.sync only)
// ---------------------------------------------------------------------------
__device__ __forceinline__ uint32_t smem_u32(const void* p) {
    return (uint32_t)__cvta_generic_to_shared(p);
}

__device__ __forceinline__ void cpa16(uint32_t dst, const void* src) {
    asm volatile("cp.async.cg.shared.global [%0], [%1], 16;" :: "r"(dst), "l"(src) : "memory");
}
#define CP_COMMIT() asm volatile("cp.async.commit_group;" ::: "memory")
#define CP_WAIT0()  asm volatile("cp.async.wait_group 0;" ::: "memory")
#define CP_WAIT1()  asm volatile("cp.async.wait_group 1;" ::: "memory")

__device__ __forceinline__ void ldsm_x4(uint32_t& r0, uint32_t& r1, uint32_t& r2, uint32_t& r3,
                                        uint32_t addr) {
    asm volatile("ldmatrix.sync.aligned.m8n8.x4.shared.b16 {%0,%1,%2,%3}, [%4];"
                 : "=r"(r0), "=r"(r1), "=r"(r2), "=r"(r3) : "r"(addr));
}
__device__ __forceinline__ void ldsm_x4t(uint32_t& r0, uint32_t& r1, uint32_t& r2, uint32_t& r3,
                                         uint32_t addr) {
    asm volatile("ldmatrix.sync.aligned.m8n8.x4.trans.shared.b16 {%0,%1,%2,%3}, [%4];"
                 : "=r"(r0), "=r"(r1), "=r"(r2), "=r"(r3) : "r"(addr));
}

__device__ __forceinline__ void mma16816(float* d, const uint32_t* a, uint32_t b0, uint32_t b1) {
    asm volatile("mma.sync.aligned.m16n8k16.row.col.f32.f16.f16.f32 "
                 "{%0,%1,%2,%3}, {%4,%5,%6,%7}, {%8,%9}, {%0,%1,%2,%3};"
                 : "+f"(d[0]), "+f"(d[1]), "+f"(d[2]), "+f"(d[3])
                 : "r"(a[0]), "r"(a[1]), "r"(a[2]), "r"(a[3]), "r"(b0), "r"(b1));
}

// pack two floats as fp16x2: lo -> low half, hi -> high half
__device__ __forceinline__ uint32_t packh2(float lo, float hi) {
    uint32_t r;
    asm("cvt.rn.f16x2.f32 %0, %1, %2;" : "=r"(r) : "f"(hi), "f"(lo));
    return r;
}
__device__ __forceinline__ float2 h2f2(uint32_t h) {
    __half2 hh = *reinterpret_cast<__half2*>(&h);
    return __half22float2(hh);
}

// ---------------------------------------------------------------------------
// Conversion kernels (batched)
// ---------------------------------------------------------------------------
__global__ __launch_bounds__(256) void conv_act3(
    const float* __restrict__ Q, const float* __restrict__ K, const float* __restrict__ V,
    __half* __restrict__ H, __half* __restrict__ L)
{
    const int z = blockIdx.y;
    const float* A = (z == 0) ? Q : (z == 1) ? K : V;
    const size_t idx = ((size_t)blockIdx.x * 256 + threadIdx.x) * 8;
    const size_t oidx = (size_t)z*ASLOT + idx;
    float4 x0 = *(const float4*)(A + idx);
    float4 x1 = *(const float4*)(A + idx + 4);
    float x[8] = {x0.x,x0.y,x0.z,x0.w,x1.x,x1.y,x1.z,x1.w};
    alignas(16) __half h8[8];
    alignas(16) __half l8[8];
    #pragma unroll
    for (int j = 0; j < 8; j++) {
        __half hi = __float2half_rn(x[j]);
        h8[j] = hi;
        l8[j] = __float2half_rn(x[j] - __half2float(hi));
    }
    *(uint4*)(H + oidx) = *(const uint4*)h8;
    *(uint4*)(L + oidx) = *(const uint4*)l8;
}

// W[k][n] fp32 -> Bt[n][k] fp16 (single precision); z over 4 weights
__global__ __launch_bounds__(256) void conv_w4(
    const float* __restrict__ W0, const float* __restrict__ W1,
    const float* __restrict__ W2, const float* __restrict__ W3,
    __half* __restrict__ H)
{
    __shared__ float t[64][65];
    const int z = blockIdx.z;
    const float* W = (z == 0) ? W0 : (z == 1) ? W1 : (z == 2) ? W2 : W3;
    const int c  = blockIdx.x;   // k block
    const int nj = blockIdx.y;   // n block

    #pragma unroll
    for (int it = 0; it < 4; it++) {
        const int idx = threadIdx.x + it*256;
        const int kr = idx >> 4;
        const int nc4 = (idx & 15)*4;
        float4 v = *(const float4*)&W[(size_t)(c*64 + kr)*1024 + nj*64 + nc4];
        t[kr][nc4+0] = v.x; t[kr][nc4+1] = v.y; t[kr][nc4+2] = v.z; t[kr][nc4+3] = v.w;
    }
    __syncthreads();

    #pragma unroll
    for (int it = 0; it < 2; it++) {
        const int item = threadIdx.x + it*256;
        const int r = item >> 3;
        const int g = item & 7;
        alignas(16) __half h8[8];
        #pragma unroll
        for (int j = 0; j < 8; j++)
            h8[j] = __float2half_rn(t[g*8 + j][r]);
        const size_t off = (size_t)z*WSLOT + (size_t)(nj*64 + r)*1024 + c*64 + g*8;
        *(uint4*)(H + off) = *(const uint4*)h8;
    }
}

// ---------------------------------------------------------------------------
// mma.sync fp16 GEMM, split-fp16 x2 (A hi/lo, B single).
// CTA 256x128x32, 512 thr, 2-stage cp.async. Batched over blockIdx.z.
// ---------------------------------------------------------------------------
#define GBM 256
#define GBN 128
#define GBK 32
#define G_A_BYTES (GBM*40*2)                     // 20480 (one plane)
#define G_B_BYTES (GBN*40*2)                     // 10240
#define G_STAGE   (2*G_A_BYTES + G_B_BYTES)      // 51200
#define G_SMEM    (2*G_STAGE)                    // 102400

#define OFF_AH(s) ((s)*G_STAGE)
#define OFF_AL(s) ((s)*G_STAGE + G_A_BYTES)
#define OFF_BH(s) ((s)*G_STAGE + 2*G_A_BYTES)

__device__ __forceinline__ void g_load_stage(
    uint32_t sb, int s, int k0, int mbase, int nbase,
    const __half* Ah, const __half* Al, const __half* Bh, int tid)
{
    #pragma unroll
    for (int i = 0; i < 2; i++) {
        const int c = tid + i*512;
        const int row = c >> 2;
        const int kc  = (c & 3) * 8;
        const size_t g = (size_t)(mbase + row)*1024 + k0 + kc;
        const uint32_t d = sb + row*80 + kc*2;
        cpa16(d + OFF_AH(s), Ah + g);
        cpa16(d + OFF_AL(s), Al + g);
    }
    {
        const int row = tid >> 2;
        const int kc  = (tid & 3) * 8;
        const size_t g = (size_t)(nbase + row)*1024 + k0 + kc;
        const uint32_t d = sb + row*80 + kc*2;
        cpa16(d + OFF_BH(s), Bh + g);
    }
}

__global__ __launch_bounds__(512, 1) void gemm_mma(
    const __half* __restrict__ Ah, const __half* __restrict__ Al,
    const __half* __restrict__ Bh,
    const float* __restrict__ bias0, const float* __restrict__ bias1,
    const float* __restrict__ bias2,
    float* __restrict__ C,
    __half* __restrict__ Ch, __half* __restrict__ Cl)
{
    extern __shared__ char smem[];
    const uint32_t sb = smem_u32(smem);
    const int tid = threadIdx.x;
    const int wid = tid >> 5;
    const int lid = tid & 31;
    const int warpM = (wid >> 2) * 64;
    const int warpN = (wid & 3) * 32;
    const int mbase = blockIdx.y * GBM;
    const int nbase = blockIdx.x * GBN;
    const int z = blockIdx.z;

    Ah += (size_t)z*ASLOT; Al += (size_t)z*ASLOT;
    Bh += (size_t)z*WSLOT;
    const float* bias = (z == 0) ? bias0 : (z == 1) ? bias1 : bias2;

    float acc[4][4][4];
    #pragma unroll
    for (int m = 0; m < 4; m++)
        #pragma unroll
        for (int n = 0; n < 4; n++)
            #pragma unroll
            for (int r = 0; r < 4; r++) acc[m][n][r] = 0.0f;

    const int aRow  = warpM + (lid & 15);
    const int aKoff = (lid >> 4) * 8;
    const int bRow  = warpN + (lid & 7) + (lid >> 4)*8;
    const int bKoff = ((lid >> 3) & 1) * 8;

    g_load_stage(sb, 0, 0, mbase, nbase, Ah, Al, Bh, tid);
    CP_COMMIT();
    g_load_stage(sb, 1, GBK, mbase, nbase, Ah, Al, Bh, tid);
    CP_COMMIT();

    for (int it = 0; it < 32; it++) {
        const int s = it & 1;
        CP_WAIT1();
        __syncthreads();

        const uint32_t aBase = sb + OFF_AH(s) + aRow*80 + aKoff*2;
        const uint32_t alBase= sb + OFF_AL(s) + aRow*80 + aKoff*2;
        const uint32_t bBase = sb + OFF_BH(s) + bRow*80 + bKoff*2;

        #pragma unroll
        for (int kk = 0; kk < 2; kk++) {
            const uint32_t kb = kk * 32;
            uint32_t af[4][4], bfr[4][2];
            #pragma unroll
            for (int p = 0; p < 2; p++) {
                uint32_t r0,r1,r2,r3;
                ldsm_x4(r0,r1,r2,r3, bBase + p*16*80 + kb);
                bfr[p*2+0][0]=r0; bfr[p*2+0][1]=r1; bfr[p*2+1][0]=r2; bfr[p*2+1][1]=r3;
            }
            #pragma unroll
            for (int m = 0; m < 4; m++)
                ldsm_x4(af[m][0], af[m][1], af[m][2], af[m][3], aBase + m*16*80 + kb);
            #pragma unroll
            for (int m = 0; m < 4; m++)
                #pragma unroll
                for (int n = 0; n < 4; n++)
                    mma16816(acc[m][n], af[m], bfr[n][0], bfr[n][1]);
            #pragma unroll
            for (int m = 0; m < 4; m++)
                ldsm_x4(af[m][0], af[m][1], af[m][2], af[m][3], alBase + m*16*80 + kb);
            #pragma unroll
            for (int m = 0; m < 4; m++)
                #pragma unroll
                for (int n = 0; n < 4; n++)
                    mma16816(acc[m][n], af[m], bfr[n][0], bfr[n][1]);
        }
        __syncthreads();
        if (it + 2 < 32)
            g_load_stage(sb, s, (it + 2)*GBK, mbase, nbase, Ah, Al, Bh, tid);
        CP_COMMIT();
    }

    // Epilogue
    const int r0base = mbase + warpM + (lid >> 2);
    const int cbase  = nbase + warpN + (lid & 3)*2;
    #pragma unroll
    for (int m = 0; m < 4; m++) {
        #pragma unroll
        for (int n = 0; n < 4; n++) {
            const int cc = cbase + n*8;
            const float2 bi = *(const float2*)&bias[cc];
            const int ra = r0base + m*16;
            float v0 = acc[m][n][0] + bi.x, v1 = acc[m][n][1] + bi.y;
            float v2 = acc[m][n][2] + bi.x, v3 = acc[m][n][3] + bi.y;
            if (C) {
                *(float2*)&C[(size_t)ra*1024 + cc] = make_float2(v0, v1);
                *(float2*)&C[(size_t)(ra + 8)*1024 + cc] = make_float2(v2, v3);
            } else {
                const size_t zo = (size_t)z*ASLOT;
                uint32_t h01 = packh2(v0, v1);
                float2 f01 = h2f2(h01);
                uint32_t l01 = packh2(v0 - f01.x, v1 - f01.y);
                uint32_t h23 = packh2(v2, v3);
                float2 f23 = h2f2(h23);
                uint32_t l23 = packh2(v2 - f23.x, v3 - f23.y);
                *(uint32_t*)&Ch[zo + (size_t)ra*1024 + cc] = h01;
                *(uint32_t*)&Cl[zo + (size_t)ra*1024 + cc] = l01;
                *(uint32_t*)&Ch[zo + (size_t)(ra + 8)*1024 + cc] = h23;
                *(uint32_t*)&Cl[zo + (size_t)(ra + 8)*1024 + cc] = l23;
            }
        }
    }
}

// ---------------------------------------------------------------------------
// Flash attention (causal), mma.sync split-fp16 x2.
// Q-tile 128 rows, 256 thr (8 warps x 16 rows). Static-max softmax,
// deferred l reduction, Q hi/lo fragments in registers.
// KV stage = K plane + V plane (single precision), 2 stages = 36864 B.
// ---------------------------------------------------------------------------
#define FKT  9216                    // 64*144: one K or V plane
#define FSTAGE (2*FKT)               // 18432 (Kh, Vh)
#define F_SMEM (2*FSTAGE)            // 36864
#define SM_SCALE 0.18033688f         // 0.125 * log2(e)

__global__ __launch_bounds__(256, 2) void flash_mma(
    const __half* __restrict__ ph, const __half* __restrict__ pl,
    __half* __restrict__ oh, __half* __restrict__ ol)
{
    extern __shared__ char smem[];
    const uint32_t sb = smem_u32(smem);
    const int tid = threadIdx.x;
    const int wid = tid >> 5;
    const int lid = tid & 31;
    const int qt  = (int)gridDim.x - 1 - (int)blockIdx.x;   // longest first
    const int bh_ = blockIdx.y;
    const int b = bh_ >> 4;
    const int h = bh_ & 15;
    const size_t base = (size_t)b * SS * DD + (size_t)h * DK;
    const __half* qh = ph;
    const __half* ql = pl;
    const __half* kh = ph + ASLOT;
    const __half* vh = ph + 2*(size_t)ASLOT;

    const int rowg0 = qt * 128;
    const int warpRow = wid * 16;
    const int nkt = 2*qt + 2;

    // Stage Q through smem, load hi/lo fragments into registers
    for (int i = tid; i < 1024; i += 256) {
        const int r = i >> 3, kc = (i & 7) * 8;
        const size_t g = base + (size_t)(rowg0 + r)*DD + kc;
        const uint32_t d = sb + r*144 + kc*2;
        cpa16(d, qh + g);
        cpa16(d + 128*144, ql + g);
    }
    CP_COMMIT();
    CP_WAIT0();
    __syncthreads();

    uint32_t qfh[4][4], qfl[4][4];
    {
        const uint32_t aAddr = sb + (warpRow + (lid & 15))*144 + ((lid >> 4)*8)*2;
        #pragma unroll
        for (int kk = 0; kk < 4; kk++) {
            ldsm_x4(qfh[kk][0], qfh[kk][1], qfh[kk][2], qfh[kk][3], aAddr + kk*32);
            ldsm_x4(qfl[kk][0], qfl[kk][1], qfl[kk][2], qfl[kk][3],
                    aAddr + 128*144 + kk*32);
        }
    }
    __syncthreads();

    // KV stages 0 and 1 (K plane + V plane each)
    #pragma unroll
    for (int s = 0; s < 2; s++) {
        const uint32_t st = sb + s*FSTAGE;
        for (int i = tid; i < 512; i += 256) {
            const int r = i >> 3, kc = (i & 7) * 8;
            const size_t g = base + (size_t)(s*64 + r)*DD + kc;
            const uint32_t d = st + r*144 + kc*2;
            cpa16(d,       kh + g);
            cpa16(d + FKT, vh + g);
        }
        CP_COMMIT();
    }

    float oacc[8][4];
    #pragma unroll
    for (int t = 0; t < 8; t++)
        #pragma unroll
        for (int r = 0; r < 4; r++) oacc[t][r] = 0.0f;
    float l0 = 0.0f, l1 = 0.0f;

    const int row0 = warpRow + (lid >> 2);
    const int row1 = row0 + 8;
    const int colB = (lid & 3) * 2;

    for (int it = 0; it < nkt; it++) {
        CP_WAIT1();
        __syncthreads();
        const uint32_t st = sb + (it & 1)*FSTAGE;
        const bool active   = (it*64) <= (rowg0 + warpRow + 15);
        const bool needmask = (it*64 + 63) > (rowg0 + warpRow);

        if (active) {
            // ---- S = Q @ K^T  ((Qh+Ql) x Kh) ----
            float sacc[8][4];
            #pragma unroll
            for (int t = 0; t < 8; t++)
                #pragma unroll
                for (int r = 0; r < 4; r++) sacc[t][r] = 0.0f;

            #pragma unroll
            for (int kk = 0; kk < 4; kk++) {
                const uint32_t kbase = st + ((lid & 7) + (lid >> 4)*8)*144
                                     + (((lid >> 3) & 1)*8 + kk*16)*2;
                #pragma unroll
                for (int p = 0; p < 4; p++) {
                    uint32_t h0,h1,h2,h3;
                    ldsm_x4(h0,h1,h2,h3, kbase + p*16*144);
                    mma16816(sacc[2*p],   qfh[kk], h0, h1);
                    mma16816(sacc[2*p],   qfl[kk], h0, h1);
                    mma16816(sacc[2*p+1], qfh[kk], h2, h3);
                    mma16816(sacc[2*p+1], qfl[kk], h2, h3);
                }
            }

            if (needmask) {
                #pragma unroll
                for (int t = 0; t < 8; t++) {
                    const int c0 = it*64 + t*8 + colB;
                    const int g0 = rowg0 + row0;
                    const int g1 = rowg0 + row1;
                    sacc[t][0] = (c0     > g0) ? -1.0e30f : sacc[t][0]*SM_SCALE;
                    sacc[t][1] = (c0 + 1 > g0) ? -1.0e30f : sacc[t][1]*SM_SCALE;
                    sacc[t][2] = (c0     > g1) ? -1.0e30f : sacc[t][2]*SM_SCALE;
                    sacc[t][3] = (c0 + 1 > g1) ? -1.0e30f : sacc[t][3]*SM_SCALE;
                }
            } else {
                #pragma unroll
                for (int t = 0; t < 8; t++)
                    #pragma unroll
                    for (int r = 0; r < 4; r++) sacc[t][r] *= SM_SCALE;
            }
            #pragma unroll
            for (int t = 0; t < 8; t++) {
                sacc[t][0] = exp2f(sacc[t][0]);
                sacc[t][1] = exp2f(sacc[t][1]);
                sacc[t][2] = exp2f(sacc[t][2]);
                sacc[t][3] = exp2f(sacc[t][3]);
                l0 += sacc[t][0] + sacc[t][1];
                l1 += sacc[t][2] + sacc[t][3];
            }

            // ---- O += P @ V  ((Ph+Pl) x Vh) ----
            #pragma unroll
            for (int kk = 0; kk < 4; kk++) {
                uint32_t ph4[4], pl4[4];
                #pragma unroll
                for (int u = 0; u < 2; u++) {
                    const int t = 2*kk + u;
                    uint32_t hA = packh2(sacc[t][0], sacc[t][1]);
                    float2 fA = h2f2(hA);
                    uint32_t hB = packh2(sacc[t][2], sacc[t][3]);
                    float2 fB = h2f2(hB);
                    ph4[2*u+0] = hA; ph4[2*u+1] = hB;
                    pl4[2*u+0] = packh2(sacc[t][0] - fA.x, sacc[t][1] - fA.y);
                    pl4[2*u+1] = packh2(sacc[t][2] - fB.x, sacc[t][3] - fB.y);
                }
                const uint32_t vbase = st + FKT
                    + (kk*16 + (lid & 7) + ((lid >> 3) & 1)*8)*144 + ((lid >> 4)*8)*2;
                #pragma unroll
                for (int p = 0; p < 4; p++) {
                    uint32_t h0,h1,h2,h3;
                    ldsm_x4t(h0,h1,h2,h3, vbase + p*32);
                    mma16816(oacc[2*p],   ph4, h0, h1);
                    mma16816(oacc[2*p],   pl4, h0, h1);
                    mma16816(oacc[2*p+1], ph4, h2, h3);
                    mma16816(oacc[2*p+1], pl4, h2, h3);
                }
            }
        }

        __syncthreads();
        if (it + 2 < nkt) {
            const uint32_t stn = sb + (it & 1)*FSTAGE;
            for (int i = tid; i < 512; i += 256) {
                const int r = i >> 3, kc = (i & 7) * 8;
                const size_t g = base + (size_t)((it + 2)*64 + r)*DD + kc;
                const uint32_t d = stn + r*144 + kc*2;
                cpa16(d,       kh + g);
                cpa16(d + FKT, vh + g);
            }
        }
        CP_COMMIT();
    }

    // epilogue: reduce l, normalize, split to fp16 hi/lo, store
    l0 += __shfl_xor_sync(0xffffffffu, l0, 1, 4);
    l0 += __shfl_xor_sync(0xffffffffu, l0, 2, 4);
    l1 += __shfl_xor_sync(0xffffffffu, l1, 1, 4);
    l1 += __shfl_xor_sync(0xffffffffu, l1, 2, 4);
    const float il0 = 1.0f / l0, il1 = 1.0f / l1;
    const size_t ga0 = base + (size_t)(rowg0 + row0)*DD + colB;
    const size_t ga1 = base + (size_t)(rowg0 + row1)*DD + colB;
    #pragma unroll
    for (int t = 0; t < 8; t++) {
        const float v0 = oacc[t][0]*il0, v1 = oacc[t][1]*il0;
        const float v2 = oacc[t][2]*il1, v3 = oacc[t][3]*il1;
        uint32_t h01 = packh2(v0, v1);
        float2 f01 = h2f2(h01);
        uint32_t l01 = packh2(v0 - f01.x, v1 - f01.y);
        uint32_t h23 = packh2(v2, v3);
        float2 f23 = h2f2(h23);
        uint32_t l23 = packh2(v2 - f23.x, v3 - f23.y);
        *(uint32_t*)&oh[ga0 + t*8] = h01;
        *(uint32_t*)&ol[ga0 + t*8] = l01;
        *(uint32_t*)&oh[ga1 + t*8] = h23;
        *(uint32_t*)&ol[ga1 + t*8] = l23;
    }
}

// ---------------------------------------------------------------------------
// Launch
// ---------------------------------------------------------------------------
extern "C" void kernel_launch(void* const* d_in, const int* in_sizes, int n_in,
                              void* d_out, int out_size)
{
    const float* Q   = (const float*)d_in[0];
    const float* K   = (const float*)d_in[1];
    const float* V   = (const float*)d_in[2];
    const float* W_q = (const float*)d_in[3];
    const float* b_q = (const float*)d_in[4];
    const float* W_k = (const float*)d_in[5];
    const float* b_k = (const float*)d_in[6];
    const float* W_v = (const float*)d_in[7];
    const float* b_v = (const float*)d_in[8];
    const float* W_o = (const float*)d_in[9];
    const float* b_o = (const float*)d_in[10];
    float* out = (float*)d_out;

    __half *xh, *xl, *ph, *pl, *oh, *ol, *bh;
    cudaGetSymbolAddress((void**)&xh, g_xh);
    cudaGetSymbolAddress((void**)&xl, g_xl);
    cudaGetSymbolAddress((void**)&ph, g_ph);
    cudaGetSymbolAddress((void**)&pl, g_pl);
    cudaGetSymbolAddress((void**)&oh, g_oh);
    cudaGetSymbolAddress((void**)&ol, g_ol);
    cudaGetSymbolAddress((void**)&bh, g_bh);

    cudaFuncSetAttribute(gemm_mma, cudaFuncAttributeMaxDynamicSharedMemorySize, G_SMEM);
    cudaFuncSetAttribute(flash_mma, cudaFuncAttributeMaxDynamicSharedMemorySize, F_SMEM);

    dim3 cwGrid(16, 16, 4);
    conv_w4<<<cwGrid, 256>>>(W_q, W_k, W_v, W_o, bh);
    dim3 caGrid(2048, 3);
    conv_act3<<<caGrid, 256>>>(Q, K, V, xh, xl);

    dim3 gGrid3(DD/GBN, MROWS/GBM, 3);   // (8,16,3)
    gemm_mma<<<gGrid3, 512, G_SMEM>>>(xh, xl, bh, b_q, b_k, b_v,
                                      nullptr, ph, pl);

    dim3 fGrid(SS/128, BB*HH);           // (16, 32)
    flash_mma<<<fGrid, 256, F_SMEM>>>(ph, pl, oh, ol);

    dim3 gGrid1(DD/GBN, MROWS/GBM, 1);
    gemm_mma<<<gGrid1, 512, G_SMEM>>>(oh, ol, bh + 3*(size_t)WSLOT,
                                      b_o, nullptr, nullptr, out, nullptr, nullptr);
}

// round 14
// speedup vs baseline: 1.5483x; 1.1154x over previous
#include <cuda_runtime.h>
#include <cuda_fp16.h>
#include <cstdint>
#include <cstddef>

// Problem constants
#define BB   2
#define SS   2048
#define DD   1024
#define HH   16
#define DK   64
#define MROWS (BB*SS)          // 4096
#define ASLOT (MROWS*DD)       // 4M elements
#define WSLOT (DD*DD)          // 1M elements

// ---------------------------------------------------------------------------
// Scratch (__device__ globals; allocation-free rule)
// ---------------------------------------------------------------------------
__device__ __half g_xh[3*ASLOT];    // activation hi (Q,K,V inputs)
__device__ __half g_xl[3*ASLOT];    // activation lo
__device__ __half g_p[3*ASLOT];     // projected q,k,v (single fp16)
__device__ __half g_oh[ASLOT];      // attention out hi
__device__ __half g_ol[ASLOT];      // attention out lo
__device__ __half g_bh[4*WSLOT];    // W^T [n][k] fp16, 4 weights (single prec)

// ---------------------------------------------------------------------------
// PTX helpers (base sm_103-safe: cp.async, ldmatrix, mma.sync only)
// ---------------------------------------------------------------------------
__device__ __forceinline__ uint32_t smem_u32(const void* p) {
    return (uint32_t)__cvta_generic_to_shared(p);
}

__device__ __forceinline__ void cpa16(uint32_t dst, const void* src) {
    asm volatile("cp.async.cg.shared.global [%0], [%1], 16;" :: "r"(dst), "l"(src) : "memory");
}
#define CP_COMMIT() asm volatile("cp.async.commit_group;" ::: "memory")
#define CP_WAIT0()  asm volatile("cp.async.wait_group 0;" ::: "memory")
#define CP_WAIT1()  asm volatile("cp.async.wait_group 1;" ::: "memory")

__device__ __forceinline__ void ldsm_x4(uint32_t& r0, uint32_t& r1, uint32_t& r2, uint32_t& r3,
                                        uint32_t addr) {
    asm volatile("ldmatrix.sync.aligned.m8n8.x4.shared.b16 {%0,%1,%2,%3}, [%4];"
                 : "=r"(r0), "=r"(r1), "=r"(r2), "=r"(r3) : "r"(addr));
}
__device__ __forceinline__ void ldsm_x4t(uint32_t& r0, uint32_t& r1, uint32_t& r2, uint32_t& r3,
                                         uint32_t addr) {
    asm volatile("ldmatrix.sync.aligned.m8n8.x4.trans.shared.b16 {%0,%1,%2,%3}, [%4];"
                 : "=r"(r0), "=r"(r1), "=r"(r2), "=r"(r3) : "r"(addr));
}

__device__ __forceinline__ void mma16816(float* d, const uint32_t* a, uint32_t b0, uint32_t b1) {
    asm volatile("mma.sync.aligned.m16n8k16.row.col.f32.f16.f16.f32 "
                 "{%0,%1,%2,%3}, {%4,%5,%6,%7}, {%8,%9}, {%0,%1,%2,%3};"
                 : "+f"(d[0]), "+f"(d[1]), "+f"(d[2]), "+f"(d[3])
                 : "r"(a[0]), "r"(a[1]), "r"(a[2]), "r"(a[3]), "r"(b0), "r"(b1));
}

// pack two floats as fp16x2: lo arg -> low half, hi arg -> high half
__device__ __forceinline__ uint32_t packh2(float lo, float hi) {
    uint32_t r;
    asm("cvt.rn.f16x2.f32 %0, %1, %2;" : "=r"(r) : "f"(hi), "f"(lo));
    return r;
}
__device__ __forceinline__ float2 h2f2(uint32_t h) {
    __half2 hh = *reinterpret_cast<__half2*>(&h);
    return __half22float2(hh);
}

// ---------------------------------------------------------------------------
// Conversion kernels (batched)
// ---------------------------------------------------------------------------
__global__ __launch_bounds__(256) void conv_act3(
    const float* __restrict__ Q, const float* __restrict__ K, const float* __restrict__ V,
    __half* __restrict__ H, __half* __restrict__ L)
{
    const int z = blockIdx.y;
    const float* A = (z == 0) ? Q : (z == 1) ? K : V;
    const size_t idx = ((size_t)blockIdx.x * 256 + threadIdx.x) * 8;
    const size_t oidx = (size_t)z*ASLOT + idx;
    float4 x0 = *(const float4*)(A + idx);
    float4 x1 = *(const float4*)(A + idx + 4);
    float x[8] = {x0.x,x0.y,x0.z,x0.w,x1.x,x1.y,x1.z,x1.w};
    alignas(16) __half h8[8];
    alignas(16) __half l8[8];
    #pragma unroll
    for (int j = 0; j < 8; j++) {
        __half hi = __float2half_rn(x[j]);
        h8[j] = hi;
        l8[j] = __float2half_rn(x[j] - __half2float(hi));
    }
    *(uint4*)(H + oidx) = *(const uint4*)h8;
    *(uint4*)(L + oidx) = *(const uint4*)l8;
}

// W[k][n] fp32 -> Bt[n][k] fp16 (single precision); z over 4 weights
__global__ __launch_bounds__(256) void conv_w4(
    const float* __restrict__ W0, const float* __restrict__ W1,
    const float* __restrict__ W2, const float* __restrict__ W3,
    __half* __restrict__ H)
{
    __shared__ float t[64][65];
    const int z = blockIdx.z;
    const float* W = (z == 0) ? W0 : (z == 1) ? W1 : (z == 2) ? W2 : W3;
    const int c  = blockIdx.x;   // k block
    const int nj = blockIdx.y;   // n block

    #pragma unroll
    for (int it = 0; it < 4; it++) {
        const int idx = threadIdx.x + it*256;
        const int kr = idx >> 4;
        const int nc4 = (idx & 15)*4;
        float4 v = *(const float4*)&W[(size_t)(c*64 + kr)*1024 + nj*64 + nc4];
        t[kr][nc4+0] = v.x; t[kr][nc4+1] = v.y; t[kr][nc4+2] = v.z; t[kr][nc4+3] = v.w;
    }
    __syncthreads();

    #pragma unroll
    for (int it = 0; it < 2; it++) {
        const int item = threadIdx.x + it*256;
        const int r = item >> 3;
        const int g = item & 7;
        alignas(16) __half h8[8];
        #pragma unroll
        for (int j = 0; j < 8; j++)
            h8[j] = __float2half_rn(t[g*8 + j][r]);
        const size_t off = (size_t)z*WSLOT + (size_t)(nj*64 + r)*1024 + c*64 + g*8;
        *(uint4*)(H + off) = *(const uint4*)h8;
    }
}

// ---------------------------------------------------------------------------
// mma.sync fp16 GEMM, split-fp16 x2 (A hi/lo, B single).
// CTA 256x128x32, 512 thr, 2-stage cp.async. Batched over blockIdx.z.
// Output: fp32 (C != nullptr) or single fp16 (Ch).
// ---------------------------------------------------------------------------
#define GBM 256
#define GBN 128
#define GBK 32
#define G_A_BYTES (GBM*40*2)                     // 20480 (one plane)
#define G_B_BYTES (GBN*40*2)                     // 10240
#define G_STAGE   (2*G_A_BYTES + G_B_BYTES)      // 51200
#define G_SMEM    (2*G_STAGE)                    // 102400

#define OFF_AH(s) ((s)*G_STAGE)
#define OFF_AL(s) ((s)*G_STAGE + G_A_BYTES)
#define OFF_BH(s) ((s)*G_STAGE + 2*G_A_BYTES)

__device__ __forceinline__ void g_load_stage(
    uint32_t sb, int s, int k0, int mbase, int nbase,
    const __half* Ah, const __half* Al, const __half* Bh, int tid)
{
    #pragma unroll
    for (int i = 0; i < 2; i++) {
        const int c = tid + i*512;
        const int row = c >> 2;
        const int kc  = (c & 3) * 8;
        const size_t g = (size_t)(mbase + row)*1024 + k0 + kc;
        const uint32_t d = sb + row*80 + kc*2;
        cpa16(d + OFF_AH(s), Ah + g);
        cpa16(d + OFF_AL(s), Al + g);
    }
    {
        const int row = tid >> 2;
        const int kc  = (tid & 3) * 8;
        const size_t g = (size_t)(nbase + row)*1024 + k0 + kc;
        const uint32_t d = sb + row*80 + kc*2;
        cpa16(d + OFF_BH(s), Bh + g);
    }
}

__global__ __launch_bounds__(512, 1) void gemm_mma(
    const __half* __restrict__ Ah, const __half* __restrict__ Al,
    const __half* __restrict__ Bh,
    const float* __restrict__ bias0, const float* __restrict__ bias1,
    const float* __restrict__ bias2,
    float* __restrict__ C, __half* __restrict__ Ch)
{
    extern __shared__ char smem[];
    const uint32_t sb = smem_u32(smem);
    const int tid = threadIdx.x;
    const int wid = tid >> 5;
    const int lid = tid & 31;
    const int warpM = (wid >> 2) * 64;
    const int warpN = (wid & 3) * 32;
    const int mbase = blockIdx.y * GBM;
    const int nbase = blockIdx.x * GBN;
    const int z = blockIdx.z;

    Ah += (size_t)z*ASLOT; Al += (size_t)z*ASLOT;
    Bh += (size_t)z*WSLOT;
    const float* bias = (z == 0) ? bias0 : (z == 1) ? bias1 : bias2;

    float acc[4][4][4];
    #pragma unroll
    for (int m = 0; m < 4; m++)
        #pragma unroll
        for (int n = 0; n < 4; n++)
            #pragma unroll
            for (int r = 0; r < 4; r++) acc[m][n][r] = 0.0f;

    const int aRow  = warpM + (lid & 15);
    const int aKoff = (lid >> 4) * 8;
    const int bRow  = warpN + (lid & 7) + (lid >> 4)*8;
    const int bKoff = ((lid >> 3) & 1) * 8;

    g_load_stage(sb, 0, 0, mbase, nbase, Ah, Al, Bh, tid);
    CP_COMMIT();
    g_load_stage(sb, 1, GBK, mbase, nbase, Ah, Al, Bh, tid);
    CP_COMMIT();

    for (int it = 0; it < 32; it++) {
        const int s = it & 1;
        CP_WAIT1();
        __syncthreads();

        const uint32_t aBase = sb + OFF_AH(s) + aRow*80 + aKoff*2;
        const uint32_t alBase= sb + OFF_AL(s) + aRow*80 + aKoff*2;
        const uint32_t bBase = sb + OFF_BH(s) + bRow*80 + bKoff*2;

        #pragma unroll
        for (int kk = 0; kk < 2; kk++) {
            const uint32_t kb = kk * 32;
            uint32_t af[4][4], bfr[4][2];
            #pragma unroll
            for (int p = 0; p < 2; p++) {
                uint32_t r0,r1,r2,r3;
                ldsm_x4(r0,r1,r2,r3, bBase + p*16*80 + kb);
                bfr[p*2+0][0]=r0; bfr[p*2+0][1]=r1; bfr[p*2+1][0]=r2; bfr[p*2+1][1]=r3;
            }
            #pragma unroll
            for (int m = 0; m < 4; m++)
                ldsm_x4(af[m][0], af[m][1], af[m][2], af[m][3], aBase + m*16*80 + kb);
            #pragma unroll
            for (int m = 0; m < 4; m++)
                #pragma unroll
                for (int n = 0; n < 4; n++)
                    mma16816(acc[m][n], af[m], bfr[n][0], bfr[n][1]);
            #pragma unroll
            for (int m = 0; m < 4; m++)
                ldsm_x4(af[m][0], af[m][1], af[m][2], af[m][3], alBase + m*16*80 + kb);
            #pragma unroll
            for (int m = 0; m < 4; m++)
                #pragma unroll
                for (int n = 0; n < 4; n++)
                    mma16816(acc[m][n], af[m], bfr[n][0], bfr[n][1]);
        }
        __syncthreads();
        if (it + 2 < 32)
            g_load_stage(sb, s, (it + 2)*GBK, mbase, nbase, Ah, Al, Bh, tid);
        CP_COMMIT();
    }

    // Epilogue
    const int r0base = mbase + warpM + (lid >> 2);
    const int cbase  = nbase + warpN + (lid & 3)*2;
    #pragma unroll
    for (int m = 0; m < 4; m++) {
        #pragma unroll
        for (int n = 0; n < 4; n++) {
            const int cc = cbase + n*8;
            const float2 bi = *(const float2*)&bias[cc];
            const int ra = r0base + m*16;
            float v0 = acc[m][n][0] + bi.x, v1 = acc[m][n][1] + bi.y;
            float v2 = acc[m][n][2] + bi.x, v3 = acc[m][n][3] + bi.y;
            if (C) {
                *(float2*)&C[(size_t)ra*1024 + cc] = make_float2(v0, v1);
                *(float2*)&C[(size_t)(ra + 8)*1024 + cc] = make_float2(v2, v3);
            } else {
                const size_t zo = (size_t)z*ASLOT;
                *(uint32_t*)&Ch[zo + (size_t)ra*1024 + cc] = packh2(v0, v1);
                *(uint32_t*)&Ch[zo + (size_t)(ra + 8)*1024 + cc] = packh2(v2, v3);
            }
        }
    }
}

// ---------------------------------------------------------------------------
// Flash attention (causal), mma.sync. QK single fp16 (softmax attenuates the
// rounding), PV split-fp16 x2 on P. Q-tile 128 rows, 256 thr (8 warps x 16
// rows). Static-max softmax, deferred l reduction, Q fragments in registers.
// KV stage = K plane + V plane, 2 stages = 36864 B, 2 CTAs/SM.
// ---------------------------------------------------------------------------
#define FKT  9216                    // 64*144: one K or V plane
#define FSTAGE (2*FKT)               // 18432 (K, V)
#define F_SMEM (2*FSTAGE)            // 36864
#define SM_SCALE 0.18033688f         // 0.125 * log2(e)

__global__ __launch_bounds__(256, 2) void flash_mma(
    const __half* __restrict__ p3,
    __half* __restrict__ oh, __half* __restrict__ ol)
{
    extern __shared__ char smem[];
    const uint32_t sb = smem_u32(smem);
    const int tid = threadIdx.x;
    const int wid = tid >> 5;
    const int lid = tid & 31;
    const int qt  = (int)gridDim.x - 1 - (int)blockIdx.x;   // longest first
    const int bh_ = blockIdx.y;
    const int b = bh_ >> 4;
    const int h = bh_ & 15;
    const size_t base = (size_t)b * SS * DD + (size_t)h * DK;
    const __half* qp = p3;
    const __half* kp = p3 + ASLOT;
    const __half* vp = p3 + 2*(size_t)ASLOT;

    const int rowg0 = qt * 128;
    const int warpRow = wid * 16;
    const int nkt = 2*qt + 2;

    // Stage Q (single plane) through smem, load fragments into registers
    for (int i = tid; i < 1024; i += 256) {
        const int r = i >> 3, kc = (i & 7) * 8;
        cpa16(sb + r*144 + kc*2, qp + base + (size_t)(rowg0 + r)*DD + kc);
    }
    CP_COMMIT();
    CP_WAIT0();
    __syncthreads();

    uint32_t qf[4][4];
    {
        const uint32_t aAddr = sb + (warpRow + (lid & 15))*144 + ((lid >> 4)*8)*2;
        #pragma unroll
        for (int kk = 0; kk < 4; kk++)
            ldsm_x4(qf[kk][0], qf[kk][1], qf[kk][2], qf[kk][3], aAddr + kk*32);
    }
    __syncthreads();

    // KV stages 0 and 1
    #pragma unroll
    for (int s = 0; s < 2; s++) {
        const uint32_t st = sb + s*FSTAGE;
        for (int i = tid; i < 512; i += 256) {
            const int r = i >> 3, kc = (i & 7) * 8;
            const size_t g = base + (size_t)(s*64 + r)*DD + kc;
            const uint32_t d = st + r*144 + kc*2;
            cpa16(d,       kp + g);
            cpa16(d + FKT, vp + g);
        }
        CP_COMMIT();
    }

    float oacc[8][4];
    #pragma unroll
    for (int t = 0; t < 8; t++)
        #pragma unroll
        for (int r = 0; r < 4; r++) oacc[t][r] = 0.0f;
    float l0 = 0.0f, l1 = 0.0f;

    const int row0 = warpRow + (lid >> 2);
    const int row1 = row0 + 8;
    const int colB = (lid & 3) * 2;

    for (int it = 0; it < nkt; it++) {
        CP_WAIT1();
        __syncthreads();
        const uint32_t st = sb + (it & 1)*FSTAGE;
        const bool active   = (it*64) <= (rowg0 + warpRow + 15);
        const bool needmask = (it*64 + 63) > (rowg0 + warpRow);

        if (active) {
            // ---- S = Q @ K^T (single fp16) ----
            float sacc[8][4];
            #pragma unroll
            for (int t = 0; t < 8; t++)
                #pragma unroll
                for (int r = 0; r < 4; r++) sacc[t][r] = 0.0f;

            #pragma unroll
            for (int kk = 0; kk < 4; kk++) {
                const uint32_t kbase = st + ((lid & 7) + (lid >> 4)*8)*144
                                     + (((lid >> 3) & 1)*8 + kk*16)*2;
                #pragma unroll
                for (int p = 0; p < 4; p++) {
                    uint32_t h0,h1,h2,h3;
                    ldsm_x4(h0,h1,h2,h3, kbase + p*16*144);
                    mma16816(sacc[2*p],   qf[kk], h0, h1);
                    mma16816(sacc[2*p+1], qf[kk], h2, h3);
                }
            }

            if (needmask) {
                #pragma unroll
                for (int t = 0; t < 8; t++) {
                    const int c0 = it*64 + t*8 + colB;
                    const int g0 = rowg0 + row0;
                    const int g1 = rowg0 + row1;
                    sacc[t][0] = (c0     > g0) ? -1.0e30f : sacc[t][0]*SM_SCALE;
                    sacc[t][1] = (c0 + 1 > g0) ? -1.0e30f : sacc[t][1]*SM_SCALE;
                    sacc[t][2] = (c0     > g1) ? -1.0e30f : sacc[t][2]*SM_SCALE;
                    sacc[t][3] = (c0 + 1 > g1) ? -1.0e30f : sacc[t][3]*SM_SCALE;
                }
            } else {
                #pragma unroll
                for (int t = 0; t < 8; t++)
                    #pragma unroll
                    for (int r = 0; r < 4; r++) sacc[t][r] *= SM_SCALE;
            }
            #pragma unroll
            for (int t = 0; t < 8; t++) {
                sacc[t][0] = exp2f(sacc[t][0]);
                sacc[t][1] = exp2f(sacc[t][1]);
                sacc[t][2] = exp2f(sacc[t][2]);
                sacc[t][3] = exp2f(sacc[t][3]);
                l0 += sacc[t][0] + sacc[t][1];
                l1 += sacc[t][2] + sacc[t][3];
            }

            // ---- O += P @ V  ((Ph+Pl) x V) ----
            #pragma unroll
            for (int kk = 0; kk < 4; kk++) {
                uint32_t ph4[4], pl4[4];
                #pragma unroll
                for (int u = 0; u < 2; u++) {
                    const int t = 2*kk + u;
                    uint32_t hA = packh2(sacc[t][0], sacc[t][1]);
                    float2 fA = h2f2(hA);
                    uint32_t hB = packh2(sacc[t][2], sacc[t][3]);
                    float2 fB = h2f2(hB);
                    ph4[2*u+0] = hA; ph4[2*u+1] = hB;
                    pl4[2*u+0] = packh2(sacc[t][0] - fA.x, sacc[t][1] - fA.y);
                    pl4[2*u+1] = packh2(sacc[t][2] - fB.x, sacc[t][3] - fB.y);
                }
                const uint32_t vbase = st + FKT
                    + (kk*16 + (lid & 7) + ((lid >> 3) & 1)*8)*144 + ((lid >> 4)*8)*2;
                #pragma unroll
                for (int p = 0; p < 4; p++) {
                    uint32_t h0,h1,h2,h3;
                    ldsm_x4t(h0,h1,h2,h3, vbase + p*32);
                    mma16816(oacc[2*p],   ph4, h0, h1);
                    mma16816(oacc[2*p],   pl4, h0, h1);
                    mma16816(oacc[2*p+1], ph4, h2, h3);
                    mma16816(oacc[2*p+1], pl4, h2, h3);
                }
            }
        }

        __syncthreads();
        if (it + 2 < nkt) {
            const uint32_t stn = sb + (it & 1)*FSTAGE;
            for (int i = tid; i < 512; i += 256) {
                const int r = i >> 3, kc = (i & 7) * 8;
                const size_t g = base + (size_t)((it + 2)*64 + r)*DD + kc;
                const uint32_t d = stn + r*144 + kc*2;
                cpa16(d,       kp + g);
                cpa16(d + FKT, vp + g);
            }
        }
        CP_COMMIT();
    }

    // epilogue: reduce l, normalize, split to fp16 hi/lo, store
    l0 += __shfl_xor_sync(0xffffffffu, l0, 1, 4);
    l0 += __shfl_xor_sync(0xffffffffu, l0, 2, 4);
    l1 += __shfl_xor_sync(0xffffffffu, l1, 1, 4);
    l1 += __shfl_xor_sync(0xffffffffu, l1, 2, 4);
    const float il0 = 1.0f / l0, il1 = 1.0f / l1;
    const size_t ga0 = base + (size_t)(rowg0 + row0)*DD + colB;
    const size_t ga1 = base + (size_t)(rowg0 + row1)*DD + colB;
    #pragma unroll
    for (int t = 0; t < 8; t++) {
        const float v0 = oacc[t][0]*il0, v1 = oacc[t][1]*il0;
        const float v2 = oacc[t][2]*il1, v3 = oacc[t][3]*il1;
        uint32_t h01 = packh2(v0, v1);
        float2 f01 = h2f2(h01);
        uint32_t l01 = packh2(v0 - f01.x, v1 - f01.y);
        uint32_t h23 = packh2(v2, v3);
        float2 f23 = h2f2(h23);
        uint32_t l23 = packh2(v2 - f23.x, v3 - f23.y);
        *(uint32_t*)&oh[ga0 + t*8] = h01;
        *(uint32_t*)&ol[ga0 + t*8] = l01;
        *(uint32_t*)&oh[ga1 + t*8] = h23;
        *(uint32_t*)&ol[ga1 + t*8] = l23;
    }
}

// ---------------------------------------------------------------------------
// Launch
// ---------------------------------------------------------------------------
extern "C" void kernel_launch(void* const* d_in, const int* in_sizes, int n_in,
                              void* d_out, int out_size)
{
    const float* Q   = (const float*)d_in[0];
    const float* K   = (const float*)d_in[1];
    const float* V   = (const float*)d_in[2];
    const float* W_q = (const float*)d_in[3];
    const float* b_q = (const float*)d_in[4];
    const float* W_k = (const float*)d_in[5];
    const float* b_k = (const float*)d_in[6];
    const float* W_v = (const float*)d_in[7];
    const float* b_v = (const float*)d_in[8];
    const float* W_o = (const float*)d_in[9];
    const float* b_o = (const float*)d_in[10];
    float* out = (float*)d_out;

    __half *xh, *xl, *pp, *oh, *ol, *bh;
    cudaGetSymbolAddress((void**)&xh, g_xh);
    cudaGetSymbolAddress((void**)&xl, g_xl);
    cudaGetSymbolAddress((void**)&pp, g_p);
    cudaGetSymbolAddress((void**)&oh, g_oh);
    cudaGetSymbolAddress((void**)&ol, g_ol);
    cudaGetSymbolAddress((void**)&bh, g_bh);

    cudaFuncSetAttribute(gemm_mma, cudaFuncAttributeMaxDynamicSharedMemorySize, G_SMEM);
    cudaFuncSetAttribute(flash_mma, cudaFuncAttributeMaxDynamicSharedMemorySize, F_SMEM);

    dim3 cwGrid(16, 16, 4);
    conv_w4<<<cwGrid, 256>>>(W_q, W_k, W_v, W_o, bh);
    dim3 caGrid(2048, 3);
    conv_act3<<<caGrid, 256>>>(Q, K, V, xh, xl);

    dim3 gGrid3(DD/GBN, MROWS/GBM, 3);   // (8,16,3)
    gemm_mma<<<gGrid3, 512, G_SMEM>>>(xh, xl, bh, b_q, b_k, b_v,
                                      nullptr, pp);

    dim3 fGrid(SS/128, BB*HH);           // (16, 32)
    flash_mma<<<fGrid, 256, F_SMEM>>>(pp, oh, ol);

    dim3 gGrid1(DD/GBN, MROWS/GBM, 1);
    gemm_mma<<<gGrid1, 512, G_SMEM>>>(oh, ol, bh + 3*(size_t)WSLOT,
                                      b_o, nullptr, nullptr, out, nullptr);
}

// round 15
// speedup vs baseline: 1.8199x; 1.1754x over previous
#include <cuda_runtime.h>
#include <cuda_fp16.h>
#include <cstdint>
#include <cstddef>

// Problem constants
#define BB   2
#define SS   2048
#define DD   1024
#define HH   16
#define DK   64
#define MROWS (BB*SS)          // 4096
#define ASLOT (MROWS*DD)       // 4M elements
#define WSLOT (DD*DD)          // 1M elements

// ---------------------------------------------------------------------------
// Scratch (__device__ globals; allocation-free rule)
// ---------------------------------------------------------------------------
__device__ __half g_xh[3*ASLOT];    // activation hi (Q,K,V inputs)
__device__ __half g_xl[3*ASLOT];    // activation lo (only V slice used)
__device__ __half g_p[3*ASLOT];     // projected q,k,v (single fp16)
__device__ __half g_oh[ASLOT];      // attention out hi
__device__ __half g_ol[ASLOT];      // attention out lo
__device__ __half g_bh[4*WSLOT];    // W^T [n][k] fp16, 4 weights

// ---------------------------------------------------------------------------
// PTX helpers (base sm_103-safe: cp.async, ldmatrix, mma.sync only)
// ---------------------------------------------------------------------------
__device__ __forceinline__ uint32_t smem_u32(const void* p) {
    return (uint32_t)__cvta_generic_to_shared(p);
}

__device__ __forceinline__ void cpa16(uint32_t dst, const void* src) {
    asm volatile("cp.async.cg.shared.global [%0], [%1], 16;" :: "r"(dst), "l"(src) : "memory");
}
#define CP_COMMIT() asm volatile("cp.async.commit_group;" ::: "memory")
#define CP_WAIT0()  asm volatile("cp.async.wait_group 0;" ::: "memory")
#define CP_WAIT1()  asm volatile("cp.async.wait_group 1;" ::: "memory")

__device__ __forceinline__ void ldsm_x4(uint32_t& r0, uint32_t& r1, uint32_t& r2, uint32_t& r3,
                                        uint32_t addr) {
    asm volatile("ldmatrix.sync.aligned.m8n8.x4.shared.b16 {%0,%1,%2,%3}, [%4];"
                 : "=r"(r0), "=r"(r1), "=r"(r2), "=r"(r3) : "r"(addr));
}
__device__ __forceinline__ void ldsm_x4t(uint32_t& r0, uint32_t& r1, uint32_t& r2, uint32_t& r3,
                                         uint32_t addr) {
    asm volatile("ldmatrix.sync.aligned.m8n8.x4.trans.shared.b16 {%0,%1,%2,%3}, [%4];"
                 : "=r"(r0), "=r"(r1), "=r"(r2), "=r"(r3) : "r"(addr));
}

__device__ __forceinline__ void mma16816(float* d, const uint32_t* a, uint32_t b0, uint32_t b1) {
    asm volatile("mma.sync.aligned.m16n8k16.row.col.f32.f16.f16.f32 "
                 "{%0,%1,%2,%3}, {%4,%5,%6,%7}, {%8,%9}, {%0,%1,%2,%3};"
                 : "+f"(d[0]), "+f"(d[1]), "+f"(d[2]), "+f"(d[3])
                 : "r"(a[0]), "r"(a[1]), "r"(a[2]), "r"(a[3]), "r"(b0), "r"(b1));
}

// pack two floats as fp16x2: lo arg -> low half, hi arg -> high half
__device__ __forceinline__ uint32_t packh2(float lo, float hi) {
    uint32_t r;
    asm("cvt.rn.f16x2.f32 %0, %1, %2;" : "=r"(r) : "f"(hi), "f"(lo));
    return r;
}
__device__ __forceinline__ float2 h2f2(uint32_t h) {
    __half2 hh = *reinterpret_cast<__half2*>(&h);
    return __half22float2(hh);
}

// ---------------------------------------------------------------------------
// Conversion kernels (batched)
// ---------------------------------------------------------------------------
__global__ __launch_bounds__(256) void conv_act3(
    const float* __restrict__ Q, const float* __restrict__ K, const float* __restrict__ V,
    __half* __restrict__ H, __half* __restrict__ L)
{
    const int z = blockIdx.y;
    const float* A = (z == 0) ? Q : (z == 1) ? K : V;
    const size_t idx = ((size_t)blockIdx.x * 256 + threadIdx.x) * 8;
    const size_t oidx = (size_t)z*ASLOT + idx;
    float4 x0 = *(const float4*)(A + idx);
    float4 x1 = *(const float4*)(A + idx + 4);
    float x[8] = {x0.x,x0.y,x0.z,x0.w,x1.x,x1.y,x1.z,x1.w};
    alignas(16) __half h8[8];
    alignas(16) __half l8[8];
    #pragma unroll
    for (int j = 0; j < 8; j++) {
        __half hi = __float2half_rn(x[j]);
        h8[j] = hi;
        l8[j] = __float2half_rn(x[j] - __half2float(hi));
    }
    *(uint4*)(H + oidx) = *(const uint4*)h8;
    if (z == 2)   // lo plane only needed for V (split projection)
        *(uint4*)(L + oidx) = *(const uint4*)l8;
}

// W[k][n] fp32 -> Bt[n][k] fp16; z over 4 weights
__global__ __launch_bounds__(256) void conv_w4(
    const float* __restrict__ W0, const float* __restrict__ W1,
    const float* __restrict__ W2, const float* __restrict__ W3,
    __half* __restrict__ H)
{
    __shared__ float t[64][65];
    const int z = blockIdx.z;
    const float* W = (z == 0) ? W0 : (z == 1) ? W1 : (z == 2) ? W2 : W3;
    const int c  = blockIdx.x;
    const int nj = blockIdx.y;

    #pragma unroll
    for (int it = 0; it < 4; it++) {
        const int idx = threadIdx.x + it*256;
        const int kr = idx >> 4;
        const int nc4 = (idx & 15)*4;
        float4 v = *(const float4*)&W[(size_t)(c*64 + kr)*1024 + nj*64 + nc4];
        t[kr][nc4+0] = v.x; t[kr][nc4+1] = v.y; t[kr][nc4+2] = v.z; t[kr][nc4+3] = v.w;
    }
    __syncthreads();

    #pragma unroll
    for (int it = 0; it < 2; it++) {
        const int item = threadIdx.x + it*256;
        const int r = item >> 3;
        const int g = item & 7;
        alignas(16) __half h8[8];
        #pragma unroll
        for (int j = 0; j < 8; j++)
            h8[j] = __float2half_rn(t[g*8 + j][r]);
        const size_t off = (size_t)z*WSLOT + (size_t)(nj*64 + r)*1024 + c*64 + g*8;
        *(uint4*)(H + off) = *(const uint4*)h8;
    }
}

// ---------------------------------------------------------------------------
// mma.sync fp16 GEMM. A-split optional per z (split_mask bit).
// CTA 256x128x32, 512 thr, 2-stage cp.async. Batched over blockIdx.z.
// ---------------------------------------------------------------------------
#define GBM 256
#define GBN 128
#define GBK 32
#define G_A_BYTES (GBM*40*2)                     // 20480 (one plane)
#define G_B_BYTES (GBN*40*2)                     // 10240
#define G_STAGE   (2*G_A_BYTES + G_B_BYTES)      // 51200
#define G_SMEM    (2*G_STAGE)                    // 102400

#define OFF_AH(s) ((s)*G_STAGE)
#define OFF_AL(s) ((s)*G_STAGE + G_A_BYTES)
#define OFF_BH(s) ((s)*G_STAGE + 2*G_A_BYTES)

__device__ __forceinline__ void g_load_stage(
    uint32_t sb, int s, int k0, int mbase, int nbase,
    const __half* Ah, const __half* Al, const __half* Bh, int tid, bool split)
{
    #pragma unroll
    for (int i = 0; i < 2; i++) {
        const int c = tid + i*512;
        const int row = c >> 2;
        const int kc  = (c & 3) * 8;
        const size_t g = (size_t)(mbase + row)*1024 + k0 + kc;
        const uint32_t d = sb + row*80 + kc*2;
        cpa16(d + OFF_AH(s), Ah + g);
        if (split) cpa16(d + OFF_AL(s), Al + g);
    }
    {
        const int row = tid >> 2;
        const int kc  = (tid & 3) * 8;
        const size_t g = (size_t)(nbase + row)*1024 + k0 + kc;
        cpa16(sb + row*80 + kc*2 + OFF_BH(s), Bh + g);
    }
}

__global__ __launch_bounds__(512, 1) void gemm_mma(
    const __half* __restrict__ Ah, const __half* __restrict__ Al,
    const __half* __restrict__ Bh,
    const float* __restrict__ bias0, const float* __restrict__ bias1,
    const float* __restrict__ bias2,
    float* __restrict__ C, __half* __restrict__ Ch, int split_mask)
{
    extern __shared__ char smem[];
    const uint32_t sb = smem_u32(smem);
    const int tid = threadIdx.x;
    const int wid = tid >> 5;
    const int lid = tid & 31;
    const int warpM = (wid >> 2) * 64;
    const int warpN = (wid & 3) * 32;
    const int mbase = blockIdx.y * GBM;
    const int nbase = blockIdx.x * GBN;
    const int z = blockIdx.z;
    const bool split = (split_mask >> z) & 1;

    Ah += (size_t)z*ASLOT; Al += (size_t)z*ASLOT;
    Bh += (size_t)z*WSLOT;
    const float* bias = (z == 0) ? bias0 : (z == 1) ? bias1 : bias2;

    float acc[4][4][4];
    #pragma unroll
    for (int m = 0; m < 4; m++)
        #pragma unroll
        for (int n = 0; n < 4; n++)
            #pragma unroll
            for (int r = 0; r < 4; r++) acc[m][n][r] = 0.0f;

    const int aRow  = warpM + (lid & 15);
    const int aKoff = (lid >> 4) * 8;
    const int bRow  = warpN + (lid & 7) + (lid >> 4)*8;
    const int bKoff = ((lid >> 3) & 1) * 8;

    g_load_stage(sb, 0, 0, mbase, nbase, Ah, Al, Bh, tid, split);
    CP_COMMIT();
    g_load_stage(sb, 1, GBK, mbase, nbase, Ah, Al, Bh, tid, split);
    CP_COMMIT();

    for (int it = 0; it < 32; it++) {
        const int s = it & 1;
        CP_WAIT1();
        __syncthreads();

        const uint32_t aBase = sb + OFF_AH(s) + aRow*80 + aKoff*2;
        const uint32_t alBase= sb + OFF_AL(s) + aRow*80 + aKoff*2;
        const uint32_t bBase = sb + OFF_BH(s) + bRow*80 + bKoff*2;

        #pragma unroll
        for (int kk = 0; kk < 2; kk++) {
            const uint32_t kb = kk * 32;
            uint32_t af[4][4], bfr[4][2];
            #pragma unroll
            for (int p = 0; p < 2; p++) {
                uint32_t r0,r1,r2,r3;
                ldsm_x4(r0,r1,r2,r3, bBase + p*16*80 + kb);
                bfr[p*2+0][0]=r0; bfr[p*2+0][1]=r1; bfr[p*2+1][0]=r2; bfr[p*2+1][1]=r3;
            }
            #pragma unroll
            for (int m = 0; m < 4; m++)
                ldsm_x4(af[m][0], af[m][1], af[m][2], af[m][3], aBase + m*16*80 + kb);
            #pragma unroll
            for (int m = 0; m < 4; m++)
                #pragma unroll
                for (int n = 0; n < 4; n++)
                    mma16816(acc[m][n], af[m], bfr[n][0], bfr[n][1]);
            if (split) {
                #pragma unroll
                for (int m = 0; m < 4; m++)
                    ldsm_x4(af[m][0], af[m][1], af[m][2], af[m][3], alBase + m*16*80 + kb);
                #pragma unroll
                for (int m = 0; m < 4; m++)
                    #pragma unroll
                    for (int n = 0; n < 4; n++)
                        mma16816(acc[m][n], af[m], bfr[n][0], bfr[n][1]);
            }
        }
        __syncthreads();
        if (it + 2 < 32)
            g_load_stage(sb, s, (it + 2)*GBK, mbase, nbase, Ah, Al, Bh, tid, split);
        CP_COMMIT();
    }

    // Epilogue
    const int r0base = mbase + warpM + (lid >> 2);
    const int cbase  = nbase + warpN + (lid & 3)*2;
    #pragma unroll
    for (int m = 0; m < 4; m++) {
        #pragma unroll
        for (int n = 0; n < 4; n++) {
            const int cc = cbase + n*8;
            const float2 bi = *(const float2*)&bias[cc];
            const int ra = r0base + m*16;
            float v0 = acc[m][n][0] + bi.x, v1 = acc[m][n][1] + bi.y;
            float v2 = acc[m][n][2] + bi.x, v3 = acc[m][n][3] + bi.y;
            if (C) {
                *(float2*)&C[(size_t)ra*1024 + cc] = make_float2(v0, v1);
                *(float2*)&C[(size_t)(ra + 8)*1024 + cc] = make_float2(v2, v3);
            } else {
                const size_t zo = (size_t)z*ASLOT;
                *(uint32_t*)&Ch[zo + (size_t)ra*1024 + cc] = packh2(v0, v1);
                *(uint32_t*)&Ch[zo + (size_t)(ra + 8)*1024 + cc] = packh2(v2, v3);
            }
        }
    }
}

// ---------------------------------------------------------------------------
// Flash attention (causal), mma.sync, all-single fp16 operands (QK and PV).
// Q-tile 128 rows, 256 thr (8 warps x 16 rows). Static-max softmax,
// deferred l reduction, Q fragments in registers.
// KV stage = K plane + V plane, 2 stages = 36864 B, 2 CTAs/SM.
// ---------------------------------------------------------------------------
#define FKT  9216                    // 64*144: one K or V plane
#define FSTAGE (2*FKT)               // 18432 (K, V)
#define F_SMEM (2*FSTAGE)            // 36864
#define SM_SCALE 0.18033688f         // 0.125 * log2(e)

__global__ __launch_bounds__(256, 2) void flash_mma(
    const __half* __restrict__ p3,
    __half* __restrict__ oh, __half* __restrict__ ol)
{
    extern __shared__ char smem[];
    const uint32_t sb = smem_u32(smem);
    const int tid = threadIdx.x;
    const int wid = tid >> 5;
    const int lid = tid & 31;
    const int qt  = (int)gridDim.x - 1 - (int)blockIdx.x;   // longest first
    const int bh_ = blockIdx.y;
    const int b = bh_ >> 4;
    const int h = bh_ & 15;
    const size_t base = (size_t)b * SS * DD + (size_t)h * DK;
    const __half* qp = p3;
    const __half* kp = p3 + ASLOT;
    const __half* vp = p3 + 2*(size_t)ASLOT;

    const int rowg0 = qt * 128;
    const int warpRow = wid * 16;
    const int nkt = 2*qt + 2;

    // Stage Q through smem, load fragments into registers
    for (int i = tid; i < 1024; i += 256) {
        const int r = i >> 3, kc = (i & 7) * 8;
        cpa16(sb + r*144 + kc*2, qp + base + (size_t)(rowg0 + r)*DD + kc);
    }
    CP_COMMIT();
    CP_WAIT0();
    __syncthreads();

    uint32_t qf[4][4];
    {
        const uint32_t aAddr = sb + (warpRow + (lid & 15))*144 + ((lid >> 4)*8)*2;
        #pragma unroll
        for (int kk = 0; kk < 4; kk++)
            ldsm_x4(qf[kk][0], qf[kk][1], qf[kk][2], qf[kk][3], aAddr + kk*32);
    }
    __syncthreads();

    // KV stages 0 and 1
    #pragma unroll
    for (int s = 0; s < 2; s++) {
        const uint32_t st = sb + s*FSTAGE;
        for (int i = tid; i < 512; i += 256) {
            const int r = i >> 3, kc = (i & 7) * 8;
            const size_t g = base + (size_t)(s*64 + r)*DD + kc;
            const uint32_t d = st + r*144 + kc*2;
            cpa16(d,       kp + g);
            cpa16(d + FKT, vp + g);
        }
        CP_COMMIT();
    }

    float oacc[8][4];
    #pragma unroll
    for (int t = 0; t < 8; t++)
        #pragma unroll
        for (int r = 0; r < 4; r++) oacc[t][r] = 0.0f;
    float l0 = 0.0f, l1 = 0.0f;

    const int row0 = warpRow + (lid >> 2);
    const int row1 = row0 + 8;
    const int colB = (lid & 3) * 2;

    for (int it = 0; it < nkt; it++) {
        CP_WAIT1();
        __syncthreads();
        const uint32_t st = sb + (it & 1)*FSTAGE;
        const bool active   = (it*64) <= (rowg0 + warpRow + 15);
        const bool needmask = (it*64 + 63) > (rowg0 + warpRow);

        if (active) {
            // ---- S = Q @ K^T ----
            float sacc[8][4];
            #pragma unroll
            for (int t = 0; t < 8; t++)
                #pragma unroll
                for (int r = 0; r < 4; r++) sacc[t][r] = 0.0f;

            #pragma unroll
            for (int kk = 0; kk < 4; kk++) {
                const uint32_t kbase = st + ((lid & 7) + (lid >> 4)*8)*144
                                     + (((lid >> 3) & 1)*8 + kk*16)*2;
                #pragma unroll
                for (int p = 0; p < 4; p++) {
                    uint32_t h0,h1,h2,h3;
                    ldsm_x4(h0,h1,h2,h3, kbase + p*16*144);
                    mma16816(sacc[2*p],   qf[kk], h0, h1);
                    mma16816(sacc[2*p+1], qf[kk], h2, h3);
                }
            }

            if (needmask) {
                #pragma unroll
                for (int t = 0; t < 8; t++) {
                    const int c0 = it*64 + t*8 + colB;
                    const int g0 = rowg0 + row0;
                    const int g1 = rowg0 + row1;
                    sacc[t][0] = (c0     > g0) ? -1.0e30f : sacc[t][0]*SM_SCALE;
                    sacc[t][1] = (c0 + 1 > g0) ? -1.0e30f : sacc[t][1]*SM_SCALE;
                    sacc[t][2] = (c0     > g1) ? -1.0e30f : sacc[t][2]*SM_SCALE;
                    sacc[t][3] = (c0 + 1 > g1) ? -1.0e30f : sacc[t][3]*SM_SCALE;
                }
            } else {
                #pragma unroll
                for (int t = 0; t < 8; t++)
                    #pragma unroll
                    for (int r = 0; r < 4; r++) sacc[t][r] *= SM_SCALE;
            }
            #pragma unroll
            for (int t = 0; t < 8; t++) {
                sacc[t][0] = exp2f(sacc[t][0]);
                sacc[t][1] = exp2f(sacc[t][1]);
                sacc[t][2] = exp2f(sacc[t][2]);
                sacc[t][3] = exp2f(sacc[t][3]);
                l0 += sacc[t][0] + sacc[t][1];
                l1 += sacc[t][2] + sacc[t][3];
            }

            // ---- O += P @ V (single fp16 P) ----
            #pragma unroll
            for (int kk = 0; kk < 4; kk++) {
                uint32_t ph4[4];
                #pragma unroll
                for (int u = 0; u < 2; u++) {
                    const int t = 2*kk + u;
                    ph4[2*u+0] = packh2(sacc[t][0], sacc[t][1]);
                    ph4[2*u+1] = packh2(sacc[t][2], sacc[t][3]);
                }
                const uint32_t vbase = st + FKT
                    + (kk*16 + (lid & 7) + ((lid >> 3) & 1)*8)*144 + ((lid >> 4)*8)*2;
                #pragma unroll
                for (int p = 0; p < 4; p++) {
                    uint32_t h0,h1,h2,h3;
                    ldsm_x4t(h0,h1,h2,h3, vbase + p*32);
                    mma16816(oacc[2*p],   ph4, h0, h1);
                    mma16816(oacc[2*p+1], ph4, h2, h3);
                }
            }
        }

        __syncthreads();
        if (it + 2 < nkt) {
            const uint32_t stn = sb + (it & 1)*FSTAGE;
            for (int i = tid; i < 512; i += 256) {
                const int r = i >> 3, kc = (i & 7) * 8;
                const size_t g = base + (size_t)((it + 2)*64 + r)*DD + kc;
                const uint32_t d = stn + r*144 + kc*2;
                cpa16(d,       kp + g);
                cpa16(d + FKT, vp + g);
            }
        }
        CP_COMMIT();
    }

    // epilogue: reduce l, normalize, split to fp16 hi/lo, store
    l0 += __shfl_xor_sync(0xffffffffu, l0, 1, 4);
    l0 += __shfl_xor_sync(0xffffffffu, l0, 2, 4);
    l1 += __shfl_xor_sync(0xffffffffu, l1, 1, 4);
    l1 += __shfl_xor_sync(0xffffffffu, l1, 2, 4);
    const float il0 = 1.0f / l0, il1 = 1.0f / l1;
    const size_t ga0 = base + (size_t)(rowg0 + row0)*DD + colB;
    const size_t ga1 = base + (size_t)(rowg0 + row1)*DD + colB;
    #pragma unroll
    for (int t = 0; t < 8; t++) {
        const float v0 = oacc[t][0]*il0, v1 = oacc[t][1]*il0;
        const float v2 = oacc[t][2]*il1, v3 = oacc[t][3]*il1;
        uint32_t h01 = packh2(v0, v1);
        float2 f01 = h2f2(h01);
        uint32_t l01 = packh2(v0 - f01.x, v1 - f01.y);
        uint32_t h23 = packh2(v2, v3);
        float2 f23 = h2f2(h23);
        uint32_t l23 = packh2(v2 - f23.x, v3 - f23.y);
        *(uint32_t*)&oh[ga0 + t*8] = h01;
        *(uint32_t*)&ol[ga0 + t*8] = l01;
        *(uint32_t*)&oh[ga1 + t*8] = h23;
        *(uint32_t*)&ol[ga1 + t*8] = l23;
    }
}

// ---------------------------------------------------------------------------
// Launch
// ---------------------------------------------------------------------------
extern "C" void kernel_launch(void* const* d_in, const int* in_sizes, int n_in,
                              void* d_out, int out_size)
{
    const float* Q   = (const float*)d_in[0];
    const float* K   = (const float*)d_in[1];
    const float* V   = (const float*)d_in[2];
    const float* W_q = (const float*)d_in[3];
    const float* b_q = (const float*)d_in[4];
    const float* W_k = (const float*)d_in[5];
    const float* b_k = (const float*)d_in[6];
    const float* W_v = (const float*)d_in[7];
    const float* b_v = (const float*)d_in[8];
    const float* W_o = (const float*)d_in[9];
    const float* b_o = (const float*)d_in[10];
    float* out = (float*)d_out;

    __half *xh, *xl, *pp, *oh, *ol, *bh;
    cudaGetSymbolAddress((void**)&xh, g_xh);
    cudaGetSymbolAddress((void**)&xl, g_xl);
    cudaGetSymbolAddress((void**)&pp, g_p);
    cudaGetSymbolAddress((void**)&oh, g_oh);
    cudaGetSymbolAddress((void**)&ol, g_ol);
    cudaGetSymbolAddress((void**)&bh, g_bh);

    cudaFuncSetAttribute(gemm_mma, cudaFuncAttributeMaxDynamicSharedMemorySize, G_SMEM);
    cudaFuncSetAttribute(flash_mma, cudaFuncAttributeMaxDynamicSharedMemorySize, F_SMEM);

    dim3 cwGrid(16, 16, 4);
    conv_w4<<<cwGrid, 256>>>(W_q, W_k, W_v, W_o, bh);
    dim3 caGrid(2048, 3);
    conv_act3<<<caGrid, 256>>>(Q, K, V, xh, xl);

    // QKV projections: split A only for V (z=2); q,k errors are softmax-attenuated
    dim3 gGrid3(DD/GBN, MROWS/GBM, 3);   // (8,16,3)
    gemm_mma<<<gGrid3, 512, G_SMEM>>>(xh, xl, bh, b_q, b_k, b_v,
                                      nullptr, pp, 0b100);

    dim3 fGrid(SS/128, BB*HH);           // (16, 32)
    flash_mma<<<fGrid, 256, F_SMEM>>>(pp, oh, ol);

    // Output projection: keep A-split (O errors hit the result directly)
    dim3 gGrid1(DD/GBN, MROWS/GBM, 1);
    gemm_mma<<<gGrid1, 512, G_SMEM>>>(oh, ol, bh + 3*(size_t)WSLOT,
                                      b_o, nullptr, nullptr, out, nullptr, 0b1);
}